// round 11
// baseline (speedup 1.0000x reference)
#include <cuda_runtime.h>
#include <math.h>

typedef unsigned long long u64;

#define T 256
#define GP 8
#define NB   16
#define NPQ  45
#define NPP  (NPQ*NPQ)
#define NTOT (NB*NPP)
#define NBLK (NTOT/GP)      /* 4050 CTAs */

/* float offsets in dynamic smem */
#define OFF_RS    0         /* 6936  : resized planar [3][8p][289] (17x17)        */
#define OFF_ACT1  6936      /* 24192 : [32ic][9iy][84] (p*9+ix); reused w3/wd/cx  */
#define OFF_ACT2  31128     /* 15360 : paired [64ic][8p][5iy][3b][2] (p str 30)   */
#define OFF_ACT3  46488     /* 4128  : [8p][516] (px*129+oc)                      */
#define OFF_RAW   50616     /* 1536  : [3][8p][64]                                */
#define OFF_W2S   52152     /* 4096  : w2 tap double buffer                       */
#define OFF_W1    56248     /* 864                                                */
#define OFF_V     57112     /* 512   : [p][64]                                    */
#define OFF_B     57624     /* 288   : b1 b2 b3 bd                                */
#define OFF_CW    57912     /* 128                                                */
#define OFF_VN2   58040     /* 8                                                  */
#define SMEM_FLOATS 58048
#define SMEM_BYTES  (SMEM_FLOATS * 4)   /* 232192 <= 232448 */

__device__ float    g_ysum[NB * 128];
__device__ unsigned g_count;

/* ---- packed fp32x2 ---- */
__device__ __forceinline__ u64 pack2(float lo, float hi) {
    u64 r; asm("mov.b64 %0, {%1, %2};" : "=l"(r) : "f"(lo), "f"(hi)); return r;
}
__device__ __forceinline__ void unpack2(u64 v, float& lo, float& hi) {
    asm("mov.b64 {%0, %1}, %2;" : "=f"(lo), "=f"(hi) : "l"(v));
}
__device__ __forceinline__ void fma2(u64& d, u64 a, u64 b) {
    asm("fma.rn.f32x2 %0, %1, %2, %0;" : "+l"(d) : "l"(a), "l"(b));
}

__device__ __forceinline__ void cp16(float* dst, const float* src) {
    unsigned s = (unsigned)__cvta_generic_to_shared(dst);
    asm volatile("cp.async.cg.shared.global [%0], [%1], 16;\n" :: "r"(s), "l"(src));
}
__device__ __forceinline__ void cp_commit() { asm volatile("cp.async.commit_group;\n"); }
__device__ __forceinline__ void cp_wait0()  { asm volatile("cp.async.wait_group 0;\n"); }

/* jax.image.resize 'linear' 8->16 */
__device__ __forceinline__ void rtab(int i, int& a0, int& a1, float& w0, float& w1) {
    if (i == 0)       { a0 = 0; a1 = 0; w0 = 1.f;   w1 = 0.f;   }
    else if (i == 15) { a0 = 7; a1 = 7; w0 = 1.f;   w1 = 0.f;   }
    else if (i & 1)   { int m = i >> 1; a0 = m;     a1 = m + 1; w0 = 0.75f; w1 = 0.25f; }
    else              { int m = i >> 1; a0 = m - 1; a1 = m;     w0 = 0.25f; w1 = 0.75f; }
}

__global__ __launch_bounds__(T, 1)
void main_kernel(const float* __restrict__ images,
                 const float* __restrict__ w1, const float* __restrict__ b1,
                 const float* __restrict__ w2, const float* __restrict__ b2,
                 const float* __restrict__ w3, const float* __restrict__ b3,
                 const float* __restrict__ wd, const float* __restrict__ bd,
                 const float* __restrict__ c_x, const float* __restrict__ c_y,
                 const float* __restrict__ comp_w, const float* __restrict__ sigma,
                 float* __restrict__ out)
{
    extern __shared__ float sm[];
    const int tid  = threadIdx.x;
    const int g0   = blockIdx.x * GP;
    const int wid  = tid >> 5;
    const int lane = tid & 31;

    float* s_b  = sm + OFF_B;
    float* s_cw = sm + OFF_CW;

    /* ---- init ---- */
    for (int i = tid; i < 864; i += T) sm[OFF_W1 + i] = w1[i];
    if (tid < 32)  s_b[tid]       = b1[tid];
    if (tid < 64)  s_b[32 + tid]  = b2[tid];
    if (tid < 128) s_b[96 + tid]  = b3[tid];
    if (tid < 64)  s_b[224 + tid] = bd[tid];
    if (tid < 128) s_cw[tid]      = comp_w[tid];
    for (int i = tid; i < OFF_RAW / 4; i += T)          /* zero rs+act1+act2p+act3 */
        ((float4*)sm)[i] = make_float4(0.f, 0.f, 0.f, 0.f);

    for (int i = tid; i < 1536; i += T) {
        int c = i >> 9, rem = i & 511, p = rem >> 6, r = rem & 63;
        int iy = r >> 3, ix = r & 7;
        int g = g0 + p, b = g / NPP, pp = g % NPP;
        int py = pp / NPQ, px = pp % NPQ;
        sm[OFF_RAW + i] = images[((b * 96 + py * 2 + iy) * 96 + px * 2 + ix) * 3 + c];
    }
    __syncthreads();

    /* ---- resize 8x8 -> 16x16 into padded 17x17 planes ---- */
    for (int i = tid; i < 6144; i += T) {
        int c = i >> 11, rem = i & 2047, p = rem >> 8, r = rem & 255;
        int oy = r >> 4, ox = r & 15;
        int ay0, ay1, ax0, ax1; float wy0, wy1, wx0, wx1;
        rtab(oy, ay0, ay1, wy0, wy1);
        rtab(ox, ax0, ax1, wx0, wx1);
        const float* rp = sm + OFF_RAW + c * 512 + p * 64;
        float v00 = rp[ay0 * 8 + ax0], v01 = rp[ay0 * 8 + ax1];
        float v10 = rp[ay1 * 8 + ax0], v11 = rp[ay1 * 8 + ax1];
        sm[OFF_RS + c * 2312 + p * 289 + oy * 17 + ox] =
            wy0 * (wx0 * v00 + wx1 * v01) + wy1 * (wx0 * v10 + wx1 * v11);
    }
    __syncthreads();

    /* ---- conv1: M=512 N=32 K=27, TM=8, TN=8; writes act1 [ic][iy*84 + p*9+ix] ---- */
    {
        const int mt = tid >> 2, ng = tid & 3;
        const int p = mt >> 3, oy = mt & 7;
        u64 acc[8][4];
        #pragma unroll
        for (int i = 0; i < 8; i++)
            #pragma unroll
            for (int j = 0; j < 4; j++) acc[i][j] = 0ull;

        #pragma unroll 1
        for (int ky = 0; ky < 3; ky++)
        #pragma unroll 1
        for (int kx = 0; kx < 3; kx++) {
            #pragma unroll
            for (int c = 0; c < 3; c++) {
                const float* ap = sm + OFF_RS + c * 2312 + p * 289 + (2 * oy + ky) * 17 + kx;
                u64 aa[8];
                #pragma unroll
                for (int ox = 0; ox < 8; ox++) { float av = ap[2 * ox]; aa[ox] = pack2(av, av); }
                const u64* wp2 = (const u64*)(sm + OFF_W1 + ((ky * 3 + kx) * 3 + c) * 32 + ng * 8);
                u64 bb[4] = {wp2[0], wp2[1], wp2[2], wp2[3]};
                #pragma unroll
                for (int ox = 0; ox < 8; ox++)
                    #pragma unroll
                    for (int j = 0; j < 4; j++)
                        fma2(acc[ox][j], aa[ox], bb[j]);
            }
        }
        #pragma unroll
        for (int j = 0; j < 4; j++) {
            int oc0 = ng * 8 + 2 * j;
            float bi0 = s_b[oc0], bi1 = s_b[oc0 + 1];
            float* op0 = sm + OFF_ACT1 + oc0 * 756 + oy * 84 + p * 9;
            float* op1 = op0 + 756;
            #pragma unroll
            for (int ox = 0; ox < 8; ox++) {
                float lo, hi; unpack2(acc[ox][j], lo, hi);
                op0[ox] = fmaxf(lo + bi0, 0.f);
                op1[ox] = fmaxf(hi + bi1, 0.f);
            }
        }
    }
    __syncthreads();

    /* ---- conv2: warp=(mh, ocq); lane=(ocg, oy, oxp, pg). Thread owns the ox-pair
           (oxp, oxp+2) and p-pair (pg, pg+2) so the epilogue writes act2 in
           conv3's paired (ix, ix+2) float2 layout directly. ---- */
    {
        const int mh  = wid >> 2;          /* p base: mh*4 */
        const int ocq = wid & 3;
        const int ocg = lane & 1;
        const int rest = lane >> 1;
        const int oy  = rest >> 2;
        const int oxp = (rest >> 1) & 1;   /* ox in {oxp, oxp+2} */
        const int pg  = rest & 1;          /* p in {mh*4+pg, mh*4+pg+2} */
        const int oc0 = ocq * 16 + ocg * 8;
        u64 acc[2][2][4];                  /* [i(p)][x(ox)][j(oc pairs)] */
        #pragma unroll
        for (int i = 0; i < 2; i++)
            #pragma unroll
            for (int x = 0; x < 2; x++)
                #pragma unroll
                for (int j = 0; j < 4; j++) acc[i][x][j] = 0ull;

        #pragma unroll
        for (int j = 0; j < 2; j++) {
            int i4 = tid + j * 256;
            cp16(sm + OFF_W2S + i4 * 4, w2 + i4 * 4);
        }
        cp_commit();

        #pragma unroll 1
        for (int t = 0; t < 9; t++) {
            cp_wait0();
            __syncthreads();
            if (t < 8) {
                #pragma unroll
                for (int j = 0; j < 2; j++) {
                    int i4 = tid + j * 256;
                    cp16(sm + OFF_W2S + ((t + 1) & 1) * 2048 + i4 * 4,
                         w2 + (t + 1) * 2048 + i4 * 4);
                }
                cp_commit();
            }
            int ky = t / 3, kx = t - ky * 3;
            const float* ab = sm + OFF_ACT1 + (2 * oy + ky) * 84
                              + (mh * 4 + pg) * 9 + 2 * oxp + kx;
            const float* wb = sm + OFF_W2S + (t & 1) * 2048 + oc0;
            #pragma unroll 8
            for (int ic = 0; ic < 32; ic++) {
                ulonglong2 wA = *(const ulonglong2*)(wb + ic * 64);
                ulonglong2 wB = *(const ulonglong2*)(wb + ic * 64 + 4);
                const float* ai = ab + ic * 756;
                #pragma unroll
                for (int i = 0; i < 2; i++)
                    #pragma unroll
                    for (int x = 0; x < 2; x++) {
                        float av = ai[i * 18 + 4 * x];
                        u64 aa = pack2(av, av);
                        fma2(acc[i][x][0], aa, wA.x);
                        fma2(acc[i][x][1], aa, wA.y);
                        fma2(acc[i][x][2], aa, wB.x);
                        fma2(acc[i][x][3], aa, wB.y);
                    }
            }
        }
        /* epilogue -> paired act2: [oc*240 + p*30 + oy*6 + b*2], b = pair base ix */
        #pragma unroll
        for (int j = 0; j < 4; j++) {
            int oc = oc0 + 2 * j;
            float bi0 = s_b[32 + oc], bi1 = s_b[32 + oc + 1];
            #pragma unroll
            for (int i = 0; i < 2; i++) {
                int p = mh * 4 + pg + 2 * i;
                float l0, h0, l1, h1;
                unpack2(acc[i][0][j], l0, h0);
                unpack2(acc[i][1][j], l1, h1);
                float r0 = fmaxf(l0 + bi0, 0.f), r1 = fmaxf(l1 + bi0, 0.f);
                float s0 = fmaxf(h0 + bi1, 0.f), s1 = fmaxf(h1 + bi1, 0.f);
                float2* b0 = (float2*)(sm + OFF_ACT2 + oc * 240 + p * 30 + oy * 6);
                float2* b1 = (float2*)(sm + OFF_ACT2 + (oc + 1) * 240 + p * 30 + oy * 6);
                if (oxp == 0) {
                    b0[0] = make_float2(r0, r1);      /* pair (ix0, ix2) */
                    b0[2] = make_float2(r1, 0.f);     /* pair (ix2, ix4=0) */
                    b1[0] = make_float2(s0, s1);
                    b1[2] = make_float2(s1, 0.f);
                } else {
                    b0[1] = make_float2(r0, r1);      /* pair (ix1, ix3) */
                    b1[1] = make_float2(s0, s1);
                }
            }
        }
    }
    __syncthreads();

    /* ---- conv3: warp = 32oc x 16m; lane = (ocg3: 4oc, mg: patch, all 4 px).
           One full-row 128B weight LDS per (tap,ic); acts via float2 pairs. ---- */
    {
        const int och = wid & 3;           /* oc0 = och*32 */
        const int mh3 = wid >> 2;          /* patches mh3*4 .. +3 */
        const int ocg3 = lane & 7;         /* 4 oc: oc = och*32 + ocg3*4 */
        const int mg  = lane >> 3;
        const int p   = mh3 * 4 + mg;
        const int oc  = och * 32 + ocg3 * 4;
        u64 acc[4][2];                     /* [px][2] : 4 oc packed */
        #pragma unroll
        for (int i = 0; i < 4; i++) { acc[i][0] = 0ull; acc[i][1] = 0ull; }

        #pragma unroll
        for (int j = 0; j < 8; j++) {
            int i4 = tid + j * 256;
            cp16(sm + OFF_ACT1 + i4 * 4, w3 + i4 * 4);
        }
        cp_commit();

        #pragma unroll
        for (int t = 0; t < 9; t++) {
            cp_wait0();
            __syncthreads();
            if (t < 8) {
                #pragma unroll
                for (int j = 0; j < 8; j++) {
                    int i4 = tid + j * 256;
                    cp16(sm + OFF_ACT1 + ((t + 1) & 1) * 8192 + i4 * 4,
                         w3 + (t + 1) * 8192 + i4 * 4);
                }
                cp_commit();
            }
            const int ky = t / 3, kx = t % 3;          /* compile-time */
            const float* wb = sm + OFF_ACT1 + (t & 1) * 8192 + oc;
            const float* ap = sm + OFF_ACT2 + p * 30 + ky * 6 + kx * 2;
            #pragma unroll 4
            for (int ic = 0; ic < 64; ic++) {
                ulonglong2 w = *(const ulonglong2*)(wb + ic * 128);   /* full-row wf */
                float2 rA = *(const float2*)(ap + ic * 240);          /* iy=ky: (ox2=0, ox2=1) */
                u64 a0 = pack2(rA.x, rA.x);
                u64 a1 = pack2(rA.y, rA.y);
                fma2(acc[0][0], a0, w.x); fma2(acc[0][1], a0, w.y);
                fma2(acc[1][0], a1, w.x); fma2(acc[1][1], a1, w.y);
                if (ky < 2) {                                          /* iy=ky+2 < 4 */
                    float2 rB = *(const float2*)(ap + ic * 240 + 12);
                    u64 a2 = pack2(rB.x, rB.x);
                    u64 a3 = pack2(rB.y, rB.y);
                    fma2(acc[2][0], a2, w.x); fma2(acc[2][1], a2, w.y);
                    fma2(acc[3][0], a3, w.x); fma2(acc[3][1], a3, w.y);
                }
            }
        }
        #pragma unroll
        for (int px = 0; px < 4; px++) {
            float v0, v1, v2, v3;
            unpack2(acc[px][0], v0, v1);
            unpack2(acc[px][1], v2, v3);
            float* o = sm + OFF_ACT3 + p * 516 + px * 129 + oc;
            o[0] = fmaxf(v0 + s_b[96 + oc],     0.f);
            o[1] = fmaxf(v1 + s_b[96 + oc + 1], 0.f);
            o[2] = fmaxf(v2 + s_b[96 + oc + 2], 0.f);
            o[3] = fmaxf(v3 + s_b[96 + oc + 3], 0.f);
        }
    }
    __syncthreads();

    /* ---- dense 512->64: warp=oc-group(8), lanes=(kq,p); butterfly K-reduce ---- */
    {
        const int oc0 = wid * 8;
        const int kq = lane >> 3, pl = lane & 7;
        u64 acc[4] = {0ull, 0ull, 0ull, 0ull};

        #pragma unroll 1
        for (int s = 0; s < 2; s++) {
            __syncthreads();
            #pragma unroll
            for (int j = 0; j < 16; j++) {
                int idx = tid + j * 256;
                int row = idx >> 4;
                int col = (idx & 15) * 4;
                int kqs = row >> 6, rr = row & 63;
                cp16(sm + OFF_ACT1 + kqs * 4104 + rr * 64 + col,
                     wd + (kqs * 128 + s * 64 + rr) * 64 + col);
            }
            cp_commit();
            cp_wait0();
            __syncthreads();

            const float* xp = sm + OFF_ACT3 + pl * 516 + kq * 129 + s * 64;
            const float* wp = sm + OFF_ACT1 + kq * 4104 + oc0;
            #pragma unroll 8
            for (int kk = 0; kk < 64; kk++) {
                float x = xp[kk];
                u64 xx = pack2(x, x);
                ulonglong2 w01 = *(const ulonglong2*)(wp + kk * 64);
                ulonglong2 w23 = *(const ulonglong2*)(wp + kk * 64 + 4);
                fma2(acc[0], xx, w01.x); fma2(acc[1], xx, w01.y);
                fma2(acc[2], xx, w23.x); fma2(acc[3], xx, w23.y);
            }
        }
        float r[8];
        #pragma unroll
        for (int j = 0; j < 4; j++) unpack2(acc[j], r[2 * j], r[2 * j + 1]);
        #pragma unroll
        for (int j = 0; j < 8; j++) {
            r[j] += __shfl_xor_sync(0xffffffffu, r[j], 8);
            r[j] += __shfl_xor_sync(0xffffffffu, r[j], 16);
        }
        if (kq == 0) {
            #pragma unroll
            for (int j = 0; j < 8; j++) {
                int e = oc0 + j;
                sm[OFF_V + pl * 64 + e] = r[j] + s_b[224 + e];
            }
        }
    }
    __syncthreads();

    /* ---- head: vn2, stage c_x (stride 65), d2 -> ow -> atomics ---- */
    if (tid < GP) {
        float a = 0.f;
        const float* vp = sm + OFF_V + tid * 64;
        #pragma unroll 8
        for (int e = 0; e < 64; e++) a = fmaf(vp[e], vp[e], a);
        sm[OFF_VN2 + tid] = a;
    }
    for (int i = tid; i < 8192; i += T) {
        int k = i >> 6, e = i & 63;
        sm[OFF_ACT1 + k * 65 + e] = c_x[i];
    }
    __syncthreads();

    {
        float inv_s2 = 1.f / (sigma[0] * sigma[0]);
        int k = tid & 127, pg = tid >> 7;
        u64 d01 = pack2(sm[OFF_VN2 + pg * 4],     sm[OFF_VN2 + pg * 4 + 1]);
        u64 d23 = pack2(sm[OFF_VN2 + pg * 4 + 2], sm[OFF_VN2 + pg * 4 + 3]);
        const u64 neg2 = pack2(-2.f, -2.f);
        const float* vp = sm + OFF_V + pg * 256;
        const float* ck = sm + OFF_ACT1 + k * 65;
        #pragma unroll 8
        for (int e = 0; e < 64; e++) {
            float cv = ck[e];
            u64 cc = pack2(cv, cv);
            u64 v01 = pack2(vp[e],       vp[64 + e]);
            u64 v23 = pack2(vp[128 + e], vp[192 + e]);
            u64 t01 = cc, t23 = cc;
            fma2(t01, neg2, v01);
            fma2(t23, neg2, v23);
            fma2(d01, cc, t01);
            fma2(d23, cc, t23);
        }
        float d[4];
        unpack2(d01, d[0], d[1]);
        unpack2(d23, d[2], d[3]);
        int b0 = (g0 + pg * 4)     / NPP;
        int b3 = (g0 + pg * 4 + 3) / NPP;
        float accA = 0.f, accB = 0.f;
        float cwk = s_cw[k];
        #pragma unroll
        for (int pp = 0; pp < 4; pp++) {
            float dd = fmaxf(d[pp], 0.f);
            float owv = fmaxf(cwk * expf(-dd * inv_s2), 1e-10f);
            int b = (g0 + pg * 4 + pp) / NPP;
            if (b == b0) accA += owv; else accB += owv;
        }
        atomicAdd(&g_ysum[b0 * 128 + k], accA);
        if (b3 != b0) atomicAdd(&g_ysum[b3 * 128 + k], accB);
    }

    /* ---- last-CTA finalize ---- */
    __syncthreads();
    __shared__ unsigned s_rank;
    if (tid == 0) {
        __threadfence();
        s_rank = atomicAdd(&g_count, 1u);
    }
    __syncthreads();
    if (s_rank == NBLK - 1) {
        __threadfence();
        float* s_y   = sm + OFF_RS;
        float* yv2   = s_y + 2048;
        float* rsum  = yv2 + 1280;
        for (int i = tid; i < NB * 128; i += T) {
            s_y[i] = g_ysum[i];
            g_ysum[i] = 0.f;
        }
        if (tid == 0) g_count = 0u;
        __syncthreads();
        for (int k = tid; k < 128; k += T) {
            float n2 = 0.f;
            #pragma unroll
            for (int i = 0; i < 10; i++) { float c = c_y[k * 10 + i]; n2 = fmaf(c, c, n2); }
            float inv = 1.f / n2;
            #pragma unroll
            for (int i = 0; i < 10; i++) { float c = c_y[k * 10 + i]; yv2[k * 10 + i] = c * c * inv; }
        }
        if (tid < NB) {
            float s = 0.f;
            for (int k = 0; k < 128; k++) s += s_y[tid * 128 + k];
            rsum[tid] = s;
        }
        __syncthreads();
        if (tid < NB * 10) {
            int b = tid / 10, i = tid % 10;
            float a = 0.f;
            for (int k = 0; k < 128; k++) a = fmaf(s_y[b * 128 + k], yv2[k * 10 + i], a);
            out[tid] = a / rsum[b];
        }
    }
}

extern "C" void kernel_launch(void* const* d_in, const int* in_sizes, int n_in,
                              void* d_out, int out_size) {
    (void)in_sizes; (void)n_in; (void)out_size;
    const float* images = (const float*)d_in[0];
    const float* w1     = (const float*)d_in[1];
    const float* b1     = (const float*)d_in[2];
    const float* w2     = (const float*)d_in[3];
    const float* b2     = (const float*)d_in[4];
    const float* w3     = (const float*)d_in[5];
    const float* b3     = (const float*)d_in[6];
    const float* wd     = (const float*)d_in[7];
    const float* bd     = (const float*)d_in[8];
    const float* c_x    = (const float*)d_in[9];
    const float* c_y    = (const float*)d_in[10];
    const float* comp_w = (const float*)d_in[11];
    const float* sigma  = (const float*)d_in[12];
    float* out = (float*)d_out;

    cudaFuncSetAttribute(main_kernel, cudaFuncAttributeMaxDynamicSharedMemorySize, SMEM_BYTES);

    main_kernel<<<NBLK, T, SMEM_BYTES>>>(images, w1, b1, w2, b2, w3, b3,
                                         wd, bd, c_x, c_y, comp_w, sigma, out);
}

// round 12
// speedup vs baseline: 1.0471x; 1.0471x over previous
#include <cuda_runtime.h>
#include <math.h>

typedef unsigned long long u64;

#define T 256
#define GP 8
#define NB   16
#define NPQ  45
#define NPP  (NPQ*NPQ)
#define NTOT (NB*NPP)
#define NBLK (NTOT/GP)      /* 4050 CTAs */

/* float offsets in dynamic smem */
#define OFF_RS    0         /* 6936  : resized planar [3][8p][289] (17x17)        */
#define OFF_ACT1  6936      /* 24192 : [32oc][9iy][p*10+ix]; reused w3/wd/cx      */
#define OFF_ACT2  31128     /* 14336 : [64oc][8p][28]; doubles as RAW during init */
#define OFF_RAW   31128     /* 1536  : [3][8p][64] (overlaps ACT2, dead by conv2) */
#define OFF_ACT3  45464     /* 4128  : [8p][516] (px*129+oc)                      */
#define OFF_W2S   49592     /* 6144  : w2 ky-group buffer (3 taps)                */
#define OFF_W1    55736     /* 864                                                */
#define OFF_V     56600     /* 512   : [p][64]                                    */
#define OFF_B     57112     /* 288   : b1 b2 b3 bd                                */
#define OFF_CW    57400     /* 128                                                */
#define OFF_VN2   57528     /* 8                                                  */
#define SMEM_FLOATS 57536
#define SMEM_BYTES  (SMEM_FLOATS * 4)   /* 230144 <= 232448 */

__device__ float    g_ysum[NB * 128];
__device__ unsigned g_count;

/* ---- packed fp32x2 ---- */
__device__ __forceinline__ u64 pack2(float lo, float hi) {
    u64 r; asm("mov.b64 %0, {%1, %2};" : "=l"(r) : "f"(lo), "f"(hi)); return r;
}
__device__ __forceinline__ void unpack2(u64 v, float& lo, float& hi) {
    asm("mov.b64 {%0, %1}, %2;" : "=f"(lo), "=f"(hi) : "l"(v));
}
__device__ __forceinline__ void fma2(u64& d, u64 a, u64 b) {
    asm("fma.rn.f32x2 %0, %1, %2, %0;" : "+l"(d) : "l"(a), "l"(b));
}

__device__ __forceinline__ void cp16(float* dst, const float* src) {
    unsigned s = (unsigned)__cvta_generic_to_shared(dst);
    asm volatile("cp.async.cg.shared.global [%0], [%1], 16;\n" :: "r"(s), "l"(src));
}
__device__ __forceinline__ void cp_commit() { asm volatile("cp.async.commit_group;\n"); }
__device__ __forceinline__ void cp_wait0()  { asm volatile("cp.async.wait_group 0;\n"); }

/* jax.image.resize 'linear' 8->16 */
__device__ __forceinline__ void rtab(int i, int& a0, int& a1, float& w0, float& w1) {
    if (i == 0)       { a0 = 0; a1 = 0; w0 = 1.f;   w1 = 0.f;   }
    else if (i == 15) { a0 = 7; a1 = 7; w0 = 1.f;   w1 = 0.f;   }
    else if (i & 1)   { int m = i >> 1; a0 = m;     a1 = m + 1; w0 = 0.75f; w1 = 0.25f; }
    else              { int m = i >> 1; a0 = m - 1; a1 = m;     w0 = 0.25f; w1 = 0.75f; }
}

__global__ __launch_bounds__(T, 1)
void main_kernel(const float* __restrict__ images,
                 const float* __restrict__ w1, const float* __restrict__ b1,
                 const float* __restrict__ w2, const float* __restrict__ b2,
                 const float* __restrict__ w3, const float* __restrict__ b3,
                 const float* __restrict__ wd, const float* __restrict__ bd,
                 const float* __restrict__ c_x, const float* __restrict__ c_y,
                 const float* __restrict__ comp_w, const float* __restrict__ sigma,
                 float* __restrict__ out)
{
    extern __shared__ float sm[];
    const int tid  = threadIdx.x;
    const int g0   = blockIdx.x * GP;
    const int wid  = tid >> 5;
    const int lane = tid & 31;

    float* s_b  = sm + OFF_B;
    float* s_cw = sm + OFF_CW;

    /* ---- init ---- */
    for (int i = tid; i < 864; i += T) sm[OFF_W1 + i] = w1[i];
    if (tid < 32)  s_b[tid]       = b1[tid];
    if (tid < 64)  s_b[32 + tid]  = b2[tid];
    if (tid < 128) s_b[96 + tid]  = b3[tid];
    if (tid < 64)  s_b[224 + tid] = bd[tid];
    if (tid < 128) s_cw[tid]      = comp_w[tid];
    for (int i = tid; i < OFF_ACT2 / 4; i += T)          /* zero rs + act1 only */
        ((float4*)sm)[i] = make_float4(0.f, 0.f, 0.f, 0.f);

    for (int i = tid; i < 1536; i += T) {
        int c = i >> 9, rem = i & 511, p = rem >> 6, r = rem & 63;
        int iy = r >> 3, ix = r & 7;
        int g = g0 + p, b = g / NPP, pp = g % NPP;
        int py = pp / NPQ, px = pp % NPQ;
        sm[OFF_RAW + i] = images[((b * 96 + py * 2 + iy) * 96 + px * 2 + ix) * 3 + c];
    }
    __syncthreads();

    /* ---- resize 8x8 -> 16x16 into padded 17x17 planes ---- */
    for (int i = tid; i < 6144; i += T) {
        int c = i >> 11, rem = i & 2047, p = rem >> 8, r = rem & 255;
        int oy = r >> 4, ox = r & 15;
        int ay0, ay1, ax0, ax1; float wy0, wy1, wx0, wx1;
        rtab(oy, ay0, ay1, wy0, wy1);
        rtab(ox, ax0, ax1, wx0, wx1);
        const float* rp = sm + OFF_RAW + c * 512 + p * 64;
        float v00 = rp[ay0 * 8 + ax0], v01 = rp[ay0 * 8 + ax1];
        float v10 = rp[ay1 * 8 + ax0], v11 = rp[ay1 * 8 + ax1];
        sm[OFF_RS + c * 2312 + p * 289 + oy * 17 + ox] =
            wy0 * (wx0 * v00 + wx1 * v01) + wy1 * (wx0 * v10 + wx1 * v11);
    }
    __syncthreads();

    /* ---- conv1: M=512 N=32 K=27, TM=8, TN=8; writes act1 [oc][iy][p*10+ix] ---- */
    {
        const int mt = tid >> 2, ng = tid & 3;
        const int p = mt >> 3, oy = mt & 7;
        u64 acc[8][4];
        #pragma unroll
        for (int i = 0; i < 8; i++)
            #pragma unroll
            for (int j = 0; j < 4; j++) acc[i][j] = 0ull;

        #pragma unroll 1
        for (int ky = 0; ky < 3; ky++)
        #pragma unroll 1
        for (int kx = 0; kx < 3; kx++) {
            #pragma unroll
            for (int c = 0; c < 3; c++) {
                const float* ap = sm + OFF_RS + c * 2312 + p * 289 + (2 * oy + ky) * 17 + kx;
                u64 aa[8];
                #pragma unroll
                for (int ox = 0; ox < 8; ox++) { float av = ap[2 * ox]; aa[ox] = pack2(av, av); }
                const u64* wp2 = (const u64*)(sm + OFF_W1 + ((ky * 3 + kx) * 3 + c) * 32 + ng * 8);
                u64 bb[4] = {wp2[0], wp2[1], wp2[2], wp2[3]};
                #pragma unroll
                for (int ox = 0; ox < 8; ox++)
                    #pragma unroll
                    for (int j = 0; j < 4; j++)
                        fma2(acc[ox][j], aa[ox], bb[j]);
            }
        }
        #pragma unroll
        for (int j = 0; j < 4; j++) {
            int oc0 = ng * 8 + 2 * j;
            float bi0 = s_b[oc0], bi1 = s_b[oc0 + 1];
            float* op0 = sm + OFF_ACT1 + oc0 * 756 + oy * 84 + p * 10;
            float* op1 = op0 + 756;
            #pragma unroll
            for (int ox = 0; ox < 8; ox++) {
                float lo, hi; unpack2(acc[ox][j], lo, hi);
                op0[ox] = fmaxf(lo + bi0, 0.f);
                op1[ox] = fmaxf(hi + bi1, 0.f);
            }
        }
    }

    /* ---- conv2: warp=(mh, ocq); lane=(ocg, pix). Acts via float2 (kx 0,1) +
           scalar (kx 2); w2 staged per ky-group (3 taps, single buffer) ---- */
    {
        const int mh  = wid >> 2;
        const int ocq = wid & 3;
        const int ocg = lane & 1;
        const int pix = lane >> 1;
        const int oy = pix >> 2, ox = pix & 3;
        const int oc0 = ocq * 16 + ocg * 8;
        u64 acc[4][4];
        #pragma unroll
        for (int i = 0; i < 4; i++)
            #pragma unroll
            for (int j = 0; j < 4; j++) acc[i][j] = 0ull;

        #pragma unroll 1
        for (int ky = 0; ky < 3; ky++) {
            __syncthreads();                       /* act1 ready (ky=0) / buffer free */
            #pragma unroll
            for (int j = 0; j < 6; j++) {
                int i4 = tid + j * 256;
                cp16(sm + OFF_W2S + i4 * 4, w2 + ky * 6144 + i4 * 4);
            }
            cp_commit();
            cp_wait0();
            __syncthreads();

            const float* ab = sm + OFF_ACT1 + (2 * oy + ky) * 84 + (mh * 4) * 10 + 2 * ox;
            #pragma unroll 4
            for (int ic = 0; ic < 32; ic++) {
                const float* ai = ab + ic * 756;
                float2 a01[4]; float a2[4];
                #pragma unroll
                for (int i = 0; i < 4; i++) {
                    a01[i] = *(const float2*)(ai + i * 10);
                    a2[i]  = ai[i * 10 + 2];
                }
                #pragma unroll
                for (int kx = 0; kx < 3; kx++) {
                    const float* wb = sm + OFF_W2S + kx * 2048 + ic * 64 + oc0;
                    ulonglong2 wA = *(const ulonglong2*)(wb);
                    ulonglong2 wB = *(const ulonglong2*)(wb + 4);
                    #pragma unroll
                    for (int i = 0; i < 4; i++) {
                        float av = (kx == 0) ? a01[i].x : (kx == 1) ? a01[i].y : a2[i];
                        u64 aa = pack2(av, av);
                        fma2(acc[i][0], aa, wA.x);
                        fma2(acc[i][1], aa, wA.y);
                        fma2(acc[i][2], aa, wB.x);
                        fma2(acc[i][3], aa, wB.y);
                    }
                }
            }
        }
        #pragma unroll
        for (int j = 0; j < 4; j++) {
            int oc = oc0 + 2 * j;
            float bi0 = s_b[32 + oc], bi1 = s_b[32 + oc + 1];
            #pragma unroll
            for (int i = 0; i < 4; i++) {
                int p = mh * 4 + i;
                float lo, hi; unpack2(acc[i][j], lo, hi);
                float* o = sm + OFF_ACT2 + oc * 224 + p * 28 + oy * 5 + ox;
                o[0]   = fmaxf(lo + bi0, 0.f);
                o[224] = fmaxf(hi + bi1, 0.f);
            }
        }
    }
    __syncthreads();

    /* ---- conv3: warp = 16 oc; lane = (m-pair, oc-octet), 2-addr weight loads ---- */
    {
        const int oc0 = wid * 16;
        const int ocg = lane & 1;
        const int mgp = lane >> 1;
        const int p   = mgp >> 1;
        const int pxh = mgp & 1;
        u64 acc[2][4];
        #pragma unroll
        for (int i = 0; i < 2; i++)
            #pragma unroll
            for (int j = 0; j < 4; j++) acc[i][j] = 0ull;

        #pragma unroll
        for (int j = 0; j < 8; j++) {
            int i4 = tid + j * 256;
            cp16(sm + OFF_ACT1 + i4 * 4, w3 + i4 * 4);
        }
        cp_commit();

        #pragma unroll 1
        for (int t = 0; t < 9; t++) {
            cp_wait0();
            __syncthreads();
            if (t < 8) {
                #pragma unroll
                for (int j = 0; j < 8; j++) {
                    int i4 = tid + j * 256;
                    cp16(sm + OFF_ACT1 + ((t + 1) & 1) * 8192 + i4 * 4,
                         w3 + (t + 1) * 8192 + i4 * 4);
                }
                cp_commit();
            }
            int ky = t / 3, kx = t - (t / 3) * 3;
            const int iy = 2 * pxh + ky;
            if (iy < 4) {
                const float* wb = sm + OFF_ACT1 + (t & 1) * 8192 + oc0 + ocg * 8;
                const float* ap = sm + OFF_ACT2 + p * 28 + iy * 5 + kx;
                #pragma unroll 4
                for (int ic = 0; ic < 64; ic++) {
                    ulonglong2 wA = *(const ulonglong2*)(wb + ic * 128);
                    ulonglong2 wB = *(const ulonglong2*)(wb + ic * 128 + 4);
                    float a0 = ap[ic * 224];
                    u64 aa0 = pack2(a0, a0);
                    fma2(acc[0][0], aa0, wA.x); fma2(acc[0][1], aa0, wA.y);
                    fma2(acc[0][2], aa0, wB.x); fma2(acc[0][3], aa0, wB.y);
                    if (kx < 2) {
                        float a1 = ap[ic * 224 + 2];
                        u64 aa1 = pack2(a1, a1);
                        fma2(acc[1][0], aa1, wA.x); fma2(acc[1][1], aa1, wA.y);
                        fma2(acc[1][2], aa1, wB.x); fma2(acc[1][3], aa1, wB.y);
                    }
                }
            }
        }
        #pragma unroll
        for (int i = 0; i < 2; i++) {
            int px = 2 * pxh + i;
            #pragma unroll
            for (int j = 0; j < 4; j++) {
                int oc = oc0 + ocg * 8 + 2 * j;
                float lo, hi; unpack2(acc[i][j], lo, hi);
                float* o = sm + OFF_ACT3 + p * 516 + px * 129 + oc;
                o[0] = fmaxf(lo + s_b[96 + oc], 0.f);
                o[1] = fmaxf(hi + s_b[96 + oc + 1], 0.f);
            }
        }
    }
    __syncthreads();

    /* ---- dense 512->64: warp=oc-group(8), lanes=(kq,p); butterfly K-reduce ---- */
    {
        const int oc0 = wid * 8;
        const int kq = lane >> 3, pl = lane & 7;
        u64 acc[4] = {0ull, 0ull, 0ull, 0ull};

        #pragma unroll 1
        for (int s = 0; s < 2; s++) {
            __syncthreads();
            #pragma unroll
            for (int j = 0; j < 16; j++) {
                int idx = tid + j * 256;
                int row = idx >> 4;
                int col = (idx & 15) * 4;
                int kqs = row >> 6, rr = row & 63;
                cp16(sm + OFF_ACT1 + kqs * 4104 + rr * 64 + col,
                     wd + (kqs * 128 + s * 64 + rr) * 64 + col);
            }
            cp_commit();
            cp_wait0();
            __syncthreads();

            const float* xp = sm + OFF_ACT3 + pl * 516 + kq * 129 + s * 64;
            const float* wp = sm + OFF_ACT1 + kq * 4104 + oc0;
            #pragma unroll 8
            for (int kk = 0; kk < 64; kk++) {
                float x = xp[kk];
                u64 xx = pack2(x, x);
                ulonglong2 w01 = *(const ulonglong2*)(wp + kk * 64);
                ulonglong2 w23 = *(const ulonglong2*)(wp + kk * 64 + 4);
                fma2(acc[0], xx, w01.x); fma2(acc[1], xx, w01.y);
                fma2(acc[2], xx, w23.x); fma2(acc[3], xx, w23.y);
            }
        }
        float r[8];
        #pragma unroll
        for (int j = 0; j < 4; j++) unpack2(acc[j], r[2 * j], r[2 * j + 1]);
        #pragma unroll
        for (int j = 0; j < 8; j++) {
            r[j] += __shfl_xor_sync(0xffffffffu, r[j], 8);
            r[j] += __shfl_xor_sync(0xffffffffu, r[j], 16);
        }
        if (kq == 0) {
            #pragma unroll
            for (int j = 0; j < 8; j++) {
                int e = oc0 + j;
                sm[OFF_V + pl * 64 + e] = r[j] + s_b[224 + e];
            }
        }
    }
    __syncthreads();

    /* ---- head: vn2, stage c_x (stride 65), d2 -> ow -> atomics ---- */
    if (tid < GP) {
        float a = 0.f;
        const float* vp = sm + OFF_V + tid * 64;
        #pragma unroll 8
        for (int e = 0; e < 64; e++) a = fmaf(vp[e], vp[e], a);
        sm[OFF_VN2 + tid] = a;
    }
    for (int i = tid; i < 8192; i += T) {
        int k = i >> 6, e = i & 63;
        sm[OFF_ACT1 + k * 65 + e] = c_x[i];
    }
    __syncthreads();

    {
        float inv_s2 = 1.f / (sigma[0] * sigma[0]);
        int k = tid & 127, pg = tid >> 7;
        u64 d01 = pack2(sm[OFF_VN2 + pg * 4],     sm[OFF_VN2 + pg * 4 + 1]);
        u64 d23 = pack2(sm[OFF_VN2 + pg * 4 + 2], sm[OFF_VN2 + pg * 4 + 3]);
        const u64 neg2 = pack2(-2.f, -2.f);
        const float* vp = sm + OFF_V + pg * 256;
        const float* ck = sm + OFF_ACT1 + k * 65;
        #pragma unroll 8
        for (int e = 0; e < 64; e++) {
            float cv = ck[e];
            u64 cc = pack2(cv, cv);
            u64 v01 = pack2(vp[e],       vp[64 + e]);
            u64 v23 = pack2(vp[128 + e], vp[192 + e]);
            u64 t01 = cc, t23 = cc;
            fma2(t01, neg2, v01);
            fma2(t23, neg2, v23);
            fma2(d01, cc, t01);
            fma2(d23, cc, t23);
        }
        float d[4];
        unpack2(d01, d[0], d[1]);
        unpack2(d23, d[2], d[3]);
        int b0 = (g0 + pg * 4)     / NPP;
        int b3 = (g0 + pg * 4 + 3) / NPP;
        float accA = 0.f, accB = 0.f;
        float cwk = s_cw[k];
        #pragma unroll
        for (int pp = 0; pp < 4; pp++) {
            float dd = fmaxf(d[pp], 0.f);
            float owv = fmaxf(cwk * __expf(-dd * inv_s2), 1e-10f);
            int b = (g0 + pg * 4 + pp) / NPP;
            if (b == b0) accA += owv; else accB += owv;
        }
        atomicAdd(&g_ysum[b0 * 128 + k], accA);
        if (b3 != b0) atomicAdd(&g_ysum[b3 * 128 + k], accB);
    }

    /* ---- last-CTA finalize ---- */
    __syncthreads();
    __shared__ unsigned s_rank;
    if (tid == 0) {
        __threadfence();
        s_rank = atomicAdd(&g_count, 1u);
    }
    __syncthreads();
    if (s_rank == NBLK - 1) {
        __threadfence();
        float* s_y   = sm + OFF_RS;
        float* yv2   = s_y + 2048;
        float* rsum  = yv2 + 1280;
        for (int i = tid; i < NB * 128; i += T) {
            s_y[i] = g_ysum[i];
            g_ysum[i] = 0.f;
        }
        if (tid == 0) g_count = 0u;
        __syncthreads();
        for (int k = tid; k < 128; k += T) {
            float n2 = 0.f;
            #pragma unroll
            for (int i = 0; i < 10; i++) { float c = c_y[k * 10 + i]; n2 = fmaf(c, c, n2); }
            float inv = 1.f / n2;
            #pragma unroll
            for (int i = 0; i < 10; i++) { float c = c_y[k * 10 + i]; yv2[k * 10 + i] = c * c * inv; }
        }
        if (tid < NB) {
            float s = 0.f;
            for (int k = 0; k < 128; k++) s += s_y[tid * 128 + k];
            rsum[tid] = s;
        }
        __syncthreads();
        if (tid < NB * 10) {
            int b = tid / 10, i = tid % 10;
            float a = 0.f;
            for (int k = 0; k < 128; k++) a = fmaf(s_y[b * 128 + k], yv2[k * 10 + i], a);
            out[tid] = a / rsum[b];
        }
    }
}

extern "C" void kernel_launch(void* const* d_in, const int* in_sizes, int n_in,
                              void* d_out, int out_size) {
    (void)in_sizes; (void)n_in; (void)out_size;
    const float* images = (const float*)d_in[0];
    const float* w1     = (const float*)d_in[1];
    const float* b1     = (const float*)d_in[2];
    const float* w2     = (const float*)d_in[3];
    const float* b2     = (const float*)d_in[4];
    const float* w3     = (const float*)d_in[5];
    const float* b3     = (const float*)d_in[6];
    const float* wd     = (const float*)d_in[7];
    const float* bd     = (const float*)d_in[8];
    const float* c_x    = (const float*)d_in[9];
    const float* c_y    = (const float*)d_in[10];
    const float* comp_w = (const float*)d_in[11];
    const float* sigma  = (const float*)d_in[12];
    float* out = (float*)d_out;

    cudaFuncSetAttribute(main_kernel, cudaFuncAttributeMaxDynamicSharedMemorySize, SMEM_BYTES);

    main_kernel<<<NBLK, T, SMEM_BYTES>>>(images, w1, b1, w2, b2, w3, b3,
                                         wd, bd, c_x, c_y, comp_w, sigma, out);
}

// round 13
// speedup vs baseline: 1.0636x; 1.0158x over previous
#include <cuda_runtime.h>
#include <math.h>

typedef unsigned long long u64;

#define T 256
#define GP 8
#define NB   16
#define NPQ  45
#define NPP  (NPQ*NPQ)
#define NTOT (NB*NPP)
#define NBLK (NTOT/GP)      /* 4050 CTAs */

/* float offsets in dynamic smem */
#define OFF_RS    0         /* 6936  : resized planar [3][8p][289] (17x17)        */
#define OFF_ACT1  6936      /* 24192 : [32oc][9iy][p*10+ix]; reused w3/wd/cx      */
#define OFF_ACT2  31128     /* 12288 : parity rows [64oc][8p][4iy][6]; RAW overlay*/
#define OFF_RAW   31128     /* 1536  : [3][8p][64] (dead before conv2 epilogue)   */
#define OFF_ACT3  43416     /* 4128  : [8p][516] (px*129+oc)                      */
#define OFF_W2S   47544     /* 6144  : w2 ky-group buffer (3 taps)                */
#define OFF_W1    53688     /* 864                                                */
#define OFF_V     54552     /* 512   : [p][64]                                    */
#define OFF_B     55064     /* 288   : b1 b2 b3 bd                                */
#define OFF_CW    55352     /* 128                                                */
#define OFF_VN2   55480     /* 8                                                  */
#define SMEM_FLOATS 55488
#define SMEM_BYTES  (SMEM_FLOATS * 4)   /* 221952 */

__device__ float    g_ysum[NB * 128];
__device__ unsigned g_count;

/* ---- packed fp32x2 ---- */
__device__ __forceinline__ u64 pack2(float lo, float hi) {
    u64 r; asm("mov.b64 %0, {%1, %2};" : "=l"(r) : "f"(lo), "f"(hi)); return r;
}
__device__ __forceinline__ void unpack2(u64 v, float& lo, float& hi) {
    asm("mov.b64 {%0, %1}, %2;" : "=f"(lo), "=f"(hi) : "l"(v));
}
__device__ __forceinline__ void fma2(u64& d, u64 a, u64 b) {
    asm("fma.rn.f32x2 %0, %1, %2, %0;" : "+l"(d) : "l"(a), "l"(b));
}

__device__ __forceinline__ void cp16(float* dst, const float* src) {
    unsigned s = (unsigned)__cvta_generic_to_shared(dst);
    asm volatile("cp.async.cg.shared.global [%0], [%1], 16;\n" :: "r"(s), "l"(src));
}
__device__ __forceinline__ void cp_commit() { asm volatile("cp.async.commit_group;\n"); }
__device__ __forceinline__ void cp_wait0()  { asm volatile("cp.async.wait_group 0;\n"); }

/* jax.image.resize 'linear' 8->16 */
__device__ __forceinline__ void rtab(int i, int& a0, int& a1, float& w0, float& w1) {
    if (i == 0)       { a0 = 0; a1 = 0; w0 = 1.f;   w1 = 0.f;   }
    else if (i == 15) { a0 = 7; a1 = 7; w0 = 1.f;   w1 = 0.f;   }
    else if (i & 1)   { int m = i >> 1; a0 = m;     a1 = m + 1; w0 = 0.75f; w1 = 0.25f; }
    else              { int m = i >> 1; a0 = m - 1; a1 = m;     w0 = 0.25f; w1 = 0.75f; }
}

__global__ __launch_bounds__(T, 1)
void main_kernel(const float* __restrict__ images,
                 const float* __restrict__ w1, const float* __restrict__ b1,
                 const float* __restrict__ w2, const float* __restrict__ b2,
                 const float* __restrict__ w3, const float* __restrict__ b3,
                 const float* __restrict__ wd, const float* __restrict__ bd,
                 const float* __restrict__ c_x, const float* __restrict__ c_y,
                 const float* __restrict__ comp_w, const float* __restrict__ sigma,
                 float* __restrict__ out)
{
    extern __shared__ float sm[];
    const int tid  = threadIdx.x;
    const int g0   = blockIdx.x * GP;
    const int wid  = tid >> 5;
    const int lane = tid & 31;

    float* s_b  = sm + OFF_B;
    float* s_cw = sm + OFF_CW;

    /* ---- init ---- */
    for (int i = tid; i < 864; i += T) sm[OFF_W1 + i] = w1[i];
    if (tid < 32)  s_b[tid]       = b1[tid];
    if (tid < 64)  s_b[32 + tid]  = b2[tid];
    if (tid < 128) s_b[96 + tid]  = b3[tid];
    if (tid < 64)  s_b[224 + tid] = bd[tid];
    if (tid < 128) s_cw[tid]      = comp_w[tid];
    for (int i = tid; i < OFF_ACT2 / 4; i += T)          /* zero rs + act1 */
        ((float4*)sm)[i] = make_float4(0.f, 0.f, 0.f, 0.f);

    for (int i = tid; i < 1536; i += T) {
        int c = i >> 9, rem = i & 511, p = rem >> 6, r = rem & 63;
        int iy = r >> 3, ix = r & 7;
        int g = g0 + p, b = g / NPP, pp = g % NPP;
        int py = pp / NPQ, px = pp % NPQ;
        sm[OFF_RAW + i] = images[((b * 96 + py * 2 + iy) * 96 + px * 2 + ix) * 3 + c];
    }
    __syncthreads();

    /* ---- resize 8x8 -> 16x16 into padded 17x17 planes ---- */
    for (int i = tid; i < 6144; i += T) {
        int c = i >> 11, rem = i & 2047, p = rem >> 8, r = rem & 255;
        int oy = r >> 4, ox = r & 15;
        int ay0, ay1, ax0, ax1; float wy0, wy1, wx0, wx1;
        rtab(oy, ay0, ay1, wy0, wy1);
        rtab(ox, ax0, ax1, wx0, wx1);
        const float* rp = sm + OFF_RAW + c * 512 + p * 64;
        float v00 = rp[ay0 * 8 + ax0], v01 = rp[ay0 * 8 + ax1];
        float v10 = rp[ay1 * 8 + ax0], v11 = rp[ay1 * 8 + ax1];
        sm[OFF_RS + c * 2312 + p * 289 + oy * 17 + ox] =
            wy0 * (wx0 * v00 + wx1 * v01) + wy1 * (wx0 * v10 + wx1 * v11);
    }
    __syncthreads();

    /* ---- prefetch w2 ky-group 0 during conv1 ---- */
    #pragma unroll
    for (int j = 0; j < 6; j++) {
        int i4 = tid + j * 256;
        cp16(sm + OFF_W2S + i4 * 4, w2 + i4 * 4);
    }
    cp_commit();

    /* ---- conv1: M=512 N=32 K=27, TM=8, TN=8; writes act1 [oc][iy][p*10+ix] ---- */
    {
        const int mt = tid >> 2, ng = tid & 3;
        const int p = mt >> 3, oy = mt & 7;
        u64 acc[8][4];
        #pragma unroll
        for (int i = 0; i < 8; i++)
            #pragma unroll
            for (int j = 0; j < 4; j++) acc[i][j] = 0ull;

        #pragma unroll 1
        for (int ky = 0; ky < 3; ky++)
        #pragma unroll 1
        for (int kx = 0; kx < 3; kx++) {
            #pragma unroll
            for (int c = 0; c < 3; c++) {
                const float* ap = sm + OFF_RS + c * 2312 + p * 289 + (2 * oy + ky) * 17 + kx;
                u64 aa[8];
                #pragma unroll
                for (int ox = 0; ox < 8; ox++) { float av = ap[2 * ox]; aa[ox] = pack2(av, av); }
                const u64* wp2 = (const u64*)(sm + OFF_W1 + ((ky * 3 + kx) * 3 + c) * 32 + ng * 8);
                u64 bb[4] = {wp2[0], wp2[1], wp2[2], wp2[3]};
                #pragma unroll
                for (int ox = 0; ox < 8; ox++)
                    #pragma unroll
                    for (int j = 0; j < 4; j++)
                        fma2(acc[ox][j], aa[ox], bb[j]);
            }
        }
        #pragma unroll
        for (int j = 0; j < 4; j++) {
            int oc0 = ng * 8 + 2 * j;
            float bi0 = s_b[oc0], bi1 = s_b[oc0 + 1];
            float* op0 = sm + OFF_ACT1 + oc0 * 756 + oy * 84 + p * 10;
            float* op1 = op0 + 756;
            #pragma unroll
            for (int ox = 0; ox < 8; ox++) {
                float lo, hi; unpack2(acc[ox][j], lo, hi);
                op0[ox] = fmaxf(lo + bi0, 0.f);
                op1[ox] = fmaxf(hi + bi1, 0.f);
            }
        }
    }

    /* ---- conv2: warp=(mh, ocq); lane=(ocg, pix); acts float2+scalar; epilogue
           writes act2 parity rows [oc*192 + p*24 + oy*6 + pos(ox)] ---- */
    {
        const int mh  = wid >> 2;
        const int ocq = wid & 3;
        const int ocg = lane & 1;
        const int pix = lane >> 1;
        const int oy = pix >> 2, ox = pix & 3;
        const int oc0 = ocq * 16 + ocg * 8;
        u64 acc[4][4];
        #pragma unroll
        for (int i = 0; i < 4; i++)
            #pragma unroll
            for (int j = 0; j < 4; j++) acc[i][j] = 0ull;

        #pragma unroll 1
        for (int ky = 0; ky < 3; ky++) {
            if (ky > 0) {
                __syncthreads();                 /* prior group fully consumed */
                #pragma unroll
                for (int j = 0; j < 6; j++) {
                    int i4 = tid + j * 256;
                    cp16(sm + OFF_W2S + i4 * 4, w2 + ky * 6144 + i4 * 4);
                }
                cp_commit();
            }
            cp_wait0();
            __syncthreads();                     /* ky=0: also orders act1 */

            const float* ab = sm + OFF_ACT1 + (2 * oy + ky) * 84 + (mh * 4) * 10 + 2 * ox;
            #pragma unroll 4
            for (int ic = 0; ic < 32; ic++) {
                const float* ai = ab + ic * 756;
                float2 a01[4]; float a2[4];
                #pragma unroll
                for (int i = 0; i < 4; i++) {
                    a01[i] = *(const float2*)(ai + i * 10);
                    a2[i]  = ai[i * 10 + 2];
                }
                #pragma unroll
                for (int kx = 0; kx < 3; kx++) {
                    const float* wb = sm + OFF_W2S + kx * 2048 + ic * 64 + oc0;
                    ulonglong2 wA = *(const ulonglong2*)(wb);
                    ulonglong2 wB = *(const ulonglong2*)(wb + 4);
                    #pragma unroll
                    for (int i = 0; i < 4; i++) {
                        float av = (kx == 0) ? a01[i].x : (kx == 1) ? a01[i].y : a2[i];
                        u64 aa = pack2(av, av);
                        fma2(acc[i][0], aa, wA.x);
                        fma2(acc[i][1], aa, wA.y);
                        fma2(acc[i][2], aa, wB.x);
                        fma2(acc[i][3], aa, wB.y);
                    }
                }
            }
        }
        const int pos = (ox & 1) ? 4 + (ox >> 1) : (ox >> 1);   /* parity group */
        #pragma unroll
        for (int j = 0; j < 4; j++) {
            int oc = oc0 + 2 * j;
            float bi0 = s_b[32 + oc], bi1 = s_b[32 + oc + 1];
            #pragma unroll
            for (int i = 0; i < 4; i++) {
                int p = mh * 4 + i;
                float lo, hi; unpack2(acc[i][j], lo, hi);
                float* o = sm + OFF_ACT2 + oc * 192 + p * 24 + oy * 6 + pos;
                o[0]   = fmaxf(lo + bi0, 0.f);
                o[192] = fmaxf(hi + bi1, 0.f);
            }
        }
    }
    __syncthreads();

    /* ---- conv3: warp = 32oc x (4p x 4px); lane = (seg: 4oc, mg: patch).
           ONE full-row 128B weight LDS per (tap,ic); acts as parity float2. ---- */
    {
        const int ocgrp = wid & 3;
        const int pgrp  = wid >> 2;
        const int seg   = lane & 7;
        const int mg    = lane >> 3;
        const int p     = pgrp * 4 + mg;
        const int oc    = ocgrp * 32 + seg * 4;
        u64 acc[4][2];                 /* [px = oy2*2+ox2][2 oc-pairs] */
        #pragma unroll
        for (int i = 0; i < 4; i++) { acc[i][0] = 0ull; acc[i][1] = 0ull; }

        #pragma unroll
        for (int j = 0; j < 8; j++) {
            int i4 = tid + j * 256;
            cp16(sm + OFF_ACT1 + i4 * 4, w3 + i4 * 4);
        }
        cp_commit();

        #pragma unroll 1
        for (int t = 0; t < 9; t++) {
            cp_wait0();
            __syncthreads();
            if (t < 8) {
                #pragma unroll
                for (int j = 0; j < 8; j++) {
                    int i4 = tid + j * 256;
                    cp16(sm + OFF_ACT1 + ((t + 1) & 1) * 8192 + i4 * 4,
                         w3 + (t + 1) * 8192 + i4 * 4);
                }
                cp_commit();
            }
            int ky = t / 3, kx = t - (t / 3) * 3;
            const float* wb = sm + OFF_ACT1 + (t & 1) * 8192 + oc;
            const float* ap = sm + OFF_ACT2 + p * 24 + ky * 6;
            if (kx < 2) {
                if (ky < 2) {
                    #pragma unroll 4
                    for (int ic = 0; ic < 64; ic++) {
                        ulonglong2 w = *(const ulonglong2*)(wb + ic * 128);
                        float2 aA = *(const float2*)(ap + ic * 192 + kx * 4);
                        float2 aB = *(const float2*)(ap + ic * 192 + 12 + kx * 4);
                        u64 a00 = pack2(aA.x, aA.x), a01 = pack2(aA.y, aA.y);
                        u64 a10 = pack2(aB.x, aB.x), a11 = pack2(aB.y, aB.y);
                        fma2(acc[0][0], a00, w.x); fma2(acc[0][1], a00, w.y);
                        fma2(acc[1][0], a01, w.x); fma2(acc[1][1], a01, w.y);
                        fma2(acc[2][0], a10, w.x); fma2(acc[2][1], a10, w.y);
                        fma2(acc[3][0], a11, w.x); fma2(acc[3][1], a11, w.y);
                    }
                } else {
                    #pragma unroll 4
                    for (int ic = 0; ic < 64; ic++) {
                        ulonglong2 w = *(const ulonglong2*)(wb + ic * 128);
                        float2 aA = *(const float2*)(ap + ic * 192 + kx * 4);
                        u64 a00 = pack2(aA.x, aA.x), a01 = pack2(aA.y, aA.y);
                        fma2(acc[0][0], a00, w.x); fma2(acc[0][1], a00, w.y);
                        fma2(acc[1][0], a01, w.x); fma2(acc[1][1], a01, w.y);
                    }
                }
            } else {
                if (ky < 2) {
                    #pragma unroll 4
                    for (int ic = 0; ic < 64; ic++) {
                        ulonglong2 w = *(const ulonglong2*)(wb + ic * 128);
                        float s0 = ap[ic * 192 + 1];        /* ix = 2 */
                        float s1 = ap[ic * 192 + 13];       /* iy+2 row, ix = 2 */
                        u64 a00 = pack2(s0, s0), a10 = pack2(s1, s1);
                        fma2(acc[0][0], a00, w.x); fma2(acc[0][1], a00, w.y);
                        fma2(acc[2][0], a10, w.x); fma2(acc[2][1], a10, w.y);
                    }
                } else {
                    #pragma unroll 4
                    for (int ic = 0; ic < 64; ic++) {
                        ulonglong2 w = *(const ulonglong2*)(wb + ic * 128);
                        float s0 = ap[ic * 192 + 1];
                        u64 a00 = pack2(s0, s0);
                        fma2(acc[0][0], a00, w.x); fma2(acc[0][1], a00, w.y);
                    }
                }
            }
        }
        #pragma unroll
        for (int px = 0; px < 4; px++) {
            float v0, v1, v2, v3;
            unpack2(acc[px][0], v0, v1);
            unpack2(acc[px][1], v2, v3);
            float* o = sm + OFF_ACT3 + p * 516 + px * 129 + oc;
            o[0] = fmaxf(v0 + s_b[96 + oc],     0.f);
            o[1] = fmaxf(v1 + s_b[96 + oc + 1], 0.f);
            o[2] = fmaxf(v2 + s_b[96 + oc + 2], 0.f);
            o[3] = fmaxf(v3 + s_b[96 + oc + 3], 0.f);
        }
    }
    __syncthreads();

    /* ---- dense 512->64: warp=oc-group(8), lanes=(kq,p); butterfly K-reduce ---- */
    {
        const int oc0 = wid * 8;
        const int kq = lane >> 3, pl = lane & 7;
        u64 acc[4] = {0ull, 0ull, 0ull, 0ull};

        #pragma unroll 1
        for (int s = 0; s < 2; s++) {
            __syncthreads();
            #pragma unroll
            for (int j = 0; j < 16; j++) {
                int idx = tid + j * 256;
                int row = idx >> 4;
                int col = (idx & 15) * 4;
                int kqs = row >> 6, rr = row & 63;
                cp16(sm + OFF_ACT1 + kqs * 4104 + rr * 64 + col,
                     wd + (kqs * 128 + s * 64 + rr) * 64 + col);
            }
            cp_commit();
            cp_wait0();
            __syncthreads();

            const float* xp = sm + OFF_ACT3 + pl * 516 + kq * 129 + s * 64;
            const float* wp = sm + OFF_ACT1 + kq * 4104 + oc0;
            #pragma unroll 8
            for (int kk = 0; kk < 64; kk++) {
                float x = xp[kk];
                u64 xx = pack2(x, x);
                ulonglong2 w01 = *(const ulonglong2*)(wp + kk * 64);
                ulonglong2 w23 = *(const ulonglong2*)(wp + kk * 64 + 4);
                fma2(acc[0], xx, w01.x); fma2(acc[1], xx, w01.y);
                fma2(acc[2], xx, w23.x); fma2(acc[3], xx, w23.y);
            }
        }
        float r[8];
        #pragma unroll
        for (int j = 0; j < 4; j++) unpack2(acc[j], r[2 * j], r[2 * j + 1]);
        #pragma unroll
        for (int j = 0; j < 8; j++) {
            r[j] += __shfl_xor_sync(0xffffffffu, r[j], 8);
            r[j] += __shfl_xor_sync(0xffffffffu, r[j], 16);
        }
        if (kq == 0) {
            #pragma unroll
            for (int j = 0; j < 8; j++) {
                int e = oc0 + j;
                sm[OFF_V + pl * 64 + e] = r[j] + s_b[224 + e];
            }
        }
    }
    __syncthreads();

    /* ---- head: vn2, stage c_x (stride 65), d2 -> ow -> atomics ---- */
    if (tid < GP) {
        float a = 0.f;
        const float* vp = sm + OFF_V + tid * 64;
        #pragma unroll 8
        for (int e = 0; e < 64; e++) a = fmaf(vp[e], vp[e], a);
        sm[OFF_VN2 + tid] = a;
    }
    for (int i = tid; i < 8192; i += T) {
        int k = i >> 6, e = i & 63;
        sm[OFF_ACT1 + k * 65 + e] = c_x[i];
    }
    __syncthreads();

    {
        float inv_s2 = 1.f / (sigma[0] * sigma[0]);
        int k = tid & 127, pg = tid >> 7;
        u64 d01 = pack2(sm[OFF_VN2 + pg * 4],     sm[OFF_VN2 + pg * 4 + 1]);
        u64 d23 = pack2(sm[OFF_VN2 + pg * 4 + 2], sm[OFF_VN2 + pg * 4 + 3]);
        const u64 neg2 = pack2(-2.f, -2.f);
        const float* vp = sm + OFF_V + pg * 256;
        const float* ck = sm + OFF_ACT1 + k * 65;
        #pragma unroll 8
        for (int e = 0; e < 64; e++) {
            float cv = ck[e];
            u64 cc = pack2(cv, cv);
            u64 v01 = pack2(vp[e],       vp[64 + e]);
            u64 v23 = pack2(vp[128 + e], vp[192 + e]);
            u64 t01 = cc, t23 = cc;
            fma2(t01, neg2, v01);
            fma2(t23, neg2, v23);
            fma2(d01, cc, t01);
            fma2(d23, cc, t23);
        }
        float d[4];
        unpack2(d01, d[0], d[1]);
        unpack2(d23, d[2], d[3]);
        int b0 = (g0 + pg * 4)     / NPP;
        int b3 = (g0 + pg * 4 + 3) / NPP;
        float accA = 0.f, accB = 0.f;
        float cwk = s_cw[k];
        #pragma unroll
        for (int pp = 0; pp < 4; pp++) {
            float dd = fmaxf(d[pp], 0.f);
            float owv = fmaxf(cwk * __expf(-dd * inv_s2), 1e-10f);
            int b = (g0 + pg * 4 + pp) / NPP;
            if (b == b0) accA += owv; else accB += owv;
        }
        atomicAdd(&g_ysum[b0 * 128 + k], accA);
        if (b3 != b0) atomicAdd(&g_ysum[b3 * 128 + k], accB);
    }

    /* ---- last-CTA finalize ---- */
    __syncthreads();
    __shared__ unsigned s_rank;
    if (tid == 0) {
        __threadfence();
        s_rank = atomicAdd(&g_count, 1u);
    }
    __syncthreads();
    if (s_rank == NBLK - 1) {
        __threadfence();
        float* s_y   = sm + OFF_RS;
        float* yv2   = s_y + 2048;
        float* rsum  = yv2 + 1280;
        for (int i = tid; i < NB * 128; i += T) {
            s_y[i] = g_ysum[i];
            g_ysum[i] = 0.f;
        }
        if (tid == 0) g_count = 0u;
        __syncthreads();
        for (int k = tid; k < 128; k += T) {
            float n2 = 0.f;
            #pragma unroll
            for (int i = 0; i < 10; i++) { float c = c_y[k * 10 + i]; n2 = fmaf(c, c, n2); }
            float inv = 1.f / n2;
            #pragma unroll
            for (int i = 0; i < 10; i++) { float c = c_y[k * 10 + i]; yv2[k * 10 + i] = c * c * inv; }
        }
        if (tid < NB) {
            float s = 0.f;
            for (int k = 0; k < 128; k++) s += s_y[tid * 128 + k];
            rsum[tid] = s;
        }
        __syncthreads();
        if (tid < NB * 10) {
            int b = tid / 10, i = tid % 10;
            float a = 0.f;
            for (int k = 0; k < 128; k++) a = fmaf(s_y[b * 128 + k], yv2[k * 10 + i], a);
            out[tid] = a / rsum[b];
        }
    }
}

extern "C" void kernel_launch(void* const* d_in, const int* in_sizes, int n_in,
                              void* d_out, int out_size) {
    (void)in_sizes; (void)n_in; (void)out_size;
    const float* images = (const float*)d_in[0];
    const float* w1     = (const float*)d_in[1];
    const float* b1     = (const float*)d_in[2];
    const float* w2     = (const float*)d_in[3];
    const float* b2     = (const float*)d_in[4];
    const float* w3     = (const float*)d_in[5];
    const float* b3     = (const float*)d_in[6];
    const float* wd     = (const float*)d_in[7];
    const float* bd     = (const float*)d_in[8];
    const float* c_x    = (const float*)d_in[9];
    const float* c_y    = (const float*)d_in[10];
    const float* comp_w = (const float*)d_in[11];
    const float* sigma  = (const float*)d_in[12];
    float* out = (float*)d_out;

    cudaFuncSetAttribute(main_kernel, cudaFuncAttributeMaxDynamicSharedMemorySize, SMEM_BYTES);

    main_kernel<<<NBLK, T, SMEM_BYTES>>>(images, w1, b1, w2, b2, w3, b3,
                                         wd, bd, c_x, c_y, comp_w, sigma, out);
}

// round 14
// speedup vs baseline: 1.0847x; 1.0198x over previous
#include <cuda_runtime.h>
#include <math.h>

typedef unsigned long long u64;

#define T 256
#define GP 8
#define NB   16
#define NPQ  45
#define NPP  (NPQ*NPQ)
#define NTOT (NB*NPP)
#define NBLK (NTOT/GP)      /* 4050 CTAs */

/* float offsets in dynamic smem */
#define OFF_RS    0         /* 6936  : resized planar; later w3-tap0 scratch (54 rows) */
#define OFF_ACT1  6936      /* 24192 : [32oc][9iy][p*10+ix]; reused w3/wd/cx           */
#define OFF_ACT2  31128     /* 12288 : parity rows [64oc][8p][4iy][6]; RAW overlay     */
#define OFF_RAW   31128     /* 1536  : [3][8p][64] (dead before conv2 epilogue)        */
#define OFF_ACT3  43416     /* 4128  : [8p][516]; +8..1287 = w3-tap0 scratch rows 54-63*/
#define OFF_W2S   47544     /* 6144  : w2 ky-group buffer (3 taps)                     */
#define OFF_W1    53688     /* 864                                                     */
#define OFF_V     54552     /* 512   : [p][64]                                         */
#define OFF_B     55064     /* 288   : b1 b2 b3 bd                                     */
#define OFF_CW    55352     /* 128                                                     */
#define OFF_VN2   55480     /* 8                                                       */
#define SMEM_FLOATS 55488
#define SMEM_BYTES  (SMEM_FLOATS * 4)   /* 221952 */

__device__ float    g_ysum[NB * 128];
__device__ unsigned g_count;

/* ---- packed fp32x2 ---- */
__device__ __forceinline__ u64 pack2(float lo, float hi) {
    u64 r; asm("mov.b64 %0, {%1, %2};" : "=l"(r) : "f"(lo), "f"(hi)); return r;
}
__device__ __forceinline__ void unpack2(u64 v, float& lo, float& hi) {
    asm("mov.b64 {%0, %1}, %2;" : "=f"(lo), "=f"(hi) : "l"(v));
}
__device__ __forceinline__ void fma2(u64& d, u64 a, u64 b) {
    asm("fma.rn.f32x2 %0, %1, %2, %0;" : "+l"(d) : "l"(a), "l"(b));
}

__device__ __forceinline__ void cp16(float* dst, const float* src) {
    unsigned s = (unsigned)__cvta_generic_to_shared(dst);
    asm volatile("cp.async.cg.shared.global [%0], [%1], 16;\n" :: "r"(s), "l"(src));
}
__device__ __forceinline__ void cp_commit() { asm volatile("cp.async.commit_group;\n"); }
__device__ __forceinline__ void cp_wait0()  { asm volatile("cp.async.wait_group 0;\n"); }

/* jax.image.resize 'linear' 8->16 */
__device__ __forceinline__ void rtab(int i, int& a0, int& a1, float& w0, float& w1) {
    if (i == 0)       { a0 = 0; a1 = 0; w0 = 1.f;   w1 = 0.f;   }
    else if (i == 15) { a0 = 7; a1 = 7; w0 = 1.f;   w1 = 0.f;   }
    else if (i & 1)   { int m = i >> 1; a0 = m;     a1 = m + 1; w0 = 0.75f; w1 = 0.25f; }
    else              { int m = i >> 1; a0 = m - 1; a1 = m;     w0 = 0.25f; w1 = 0.75f; }
}

__global__ __launch_bounds__(T, 1)
void main_kernel(const float* __restrict__ images,
                 const float* __restrict__ w1, const float* __restrict__ b1,
                 const float* __restrict__ w2, const float* __restrict__ b2,
                 const float* __restrict__ w3, const float* __restrict__ b3,
                 const float* __restrict__ wd, const float* __restrict__ bd,
                 const float* __restrict__ c_x, const float* __restrict__ c_y,
                 const float* __restrict__ comp_w, const float* __restrict__ sigma,
                 float* __restrict__ out)
{
    extern __shared__ float sm[];
    const int tid  = threadIdx.x;
    const int g0   = blockIdx.x * GP;
    const int wid  = tid >> 5;
    const int lane = tid & 31;

    float* s_b  = sm + OFF_B;
    float* s_cw = sm + OFF_CW;

    /* ---- init ---- */
    for (int i = tid; i < 864; i += T) sm[OFF_W1 + i] = w1[i];
    if (tid < 32)  s_b[tid]       = b1[tid];
    if (tid < 64)  s_b[32 + tid]  = b2[tid];
    if (tid < 128) s_b[96 + tid]  = b3[tid];
    if (tid < 64)  s_b[224 + tid] = bd[tid];
    if (tid < 128) s_cw[tid]      = comp_w[tid];
    for (int i = tid; i < OFF_ACT2 / 4; i += T)          /* zero rs + act1 */
        ((float4*)sm)[i] = make_float4(0.f, 0.f, 0.f, 0.f);

    for (int i = tid; i < 1536; i += T) {
        int c = i >> 9, rem = i & 511, p = rem >> 6, r = rem & 63;
        int iy = r >> 3, ix = r & 7;
        int g = g0 + p, b = g / NPP, pp = g % NPP;
        int py = pp / NPQ, px = pp % NPQ;
        sm[OFF_RAW + i] = images[((b * 96 + py * 2 + iy) * 96 + px * 2 + ix) * 3 + c];
    }
    __syncthreads();

    /* ---- resize 8x8 -> 16x16 into padded 17x17 planes ---- */
    for (int i = tid; i < 6144; i += T) {
        int c = i >> 11, rem = i & 2047, p = rem >> 8, r = rem & 255;
        int oy = r >> 4, ox = r & 15;
        int ay0, ay1, ax0, ax1; float wy0, wy1, wx0, wx1;
        rtab(oy, ay0, ay1, wy0, wy1);
        rtab(ox, ax0, ax1, wx0, wx1);
        const float* rp = sm + OFF_RAW + c * 512 + p * 64;
        float v00 = rp[ay0 * 8 + ax0], v01 = rp[ay0 * 8 + ax1];
        float v10 = rp[ay1 * 8 + ax0], v11 = rp[ay1 * 8 + ax1];
        sm[OFF_RS + c * 2312 + p * 289 + oy * 17 + ox] =
            wy0 * (wx0 * v00 + wx1 * v01) + wy1 * (wx0 * v10 + wx1 * v11);
    }
    __syncthreads();

    /* ---- prefetch w2 ky-group 0 during conv1 ---- */
    #pragma unroll
    for (int j = 0; j < 6; j++) {
        int i4 = tid + j * 256;
        cp16(sm + OFF_W2S + i4 * 4, w2 + i4 * 4);
    }
    cp_commit();

    /* ---- conv1: M=512 N=32 K=27, TM=8, TN=8; writes act1 [oc][iy][p*10+ix] ---- */
    {
        const int mt = tid >> 2, ng = tid & 3;
        const int p = mt >> 3, oy = mt & 7;
        u64 acc[8][4];
        #pragma unroll
        for (int i = 0; i < 8; i++)
            #pragma unroll
            for (int j = 0; j < 4; j++) acc[i][j] = 0ull;

        #pragma unroll 1
        for (int ky = 0; ky < 3; ky++)
        #pragma unroll 1
        for (int kx = 0; kx < 3; kx++) {
            #pragma unroll
            for (int c = 0; c < 3; c++) {
                const float* ap = sm + OFF_RS + c * 2312 + p * 289 + (2 * oy + ky) * 17 + kx;
                u64 aa[8];
                #pragma unroll
                for (int ox = 0; ox < 8; ox++) { float av = ap[2 * ox]; aa[ox] = pack2(av, av); }
                const u64* wp2 = (const u64*)(sm + OFF_W1 + ((ky * 3 + kx) * 3 + c) * 32 + ng * 8);
                u64 bb[4] = {wp2[0], wp2[1], wp2[2], wp2[3]};
                #pragma unroll
                for (int ox = 0; ox < 8; ox++)
                    #pragma unroll
                    for (int j = 0; j < 4; j++)
                        fma2(acc[ox][j], aa[ox], bb[j]);
            }
        }
        #pragma unroll
        for (int j = 0; j < 4; j++) {
            int oc0 = ng * 8 + 2 * j;
            float bi0 = s_b[oc0], bi1 = s_b[oc0 + 1];
            float* op0 = sm + OFF_ACT1 + oc0 * 756 + oy * 84 + p * 10;
            float* op1 = op0 + 756;
            #pragma unroll
            for (int ox = 0; ox < 8; ox++) {
                float lo, hi; unpack2(acc[ox][j], lo, hi);
                op0[ox] = fmaxf(lo + bi0, 0.f);
                op1[ox] = fmaxf(hi + bi1, 0.f);
            }
        }
    }

    /* ---- conv2: warp=(mh, ocq); lane=(ocg, pix); acts float2+scalar.
           At ky==2, prefetch w3 tap0 into scratch (RS rows 0-53, ACT3+8 rows 54-63) ---- */
    {
        const int mh  = wid >> 2;
        const int ocq = wid & 3;
        const int ocg = lane & 1;
        const int pix = lane >> 1;
        const int oy = pix >> 2, ox = pix & 3;
        const int oc0 = ocq * 16 + ocg * 8;
        u64 acc[4][4];
        #pragma unroll
        for (int i = 0; i < 4; i++)
            #pragma unroll
            for (int j = 0; j < 4; j++) acc[i][j] = 0ull;

        #pragma unroll 1
        for (int ky = 0; ky < 3; ky++) {
            if (ky > 0) {
                __syncthreads();                 /* prior group fully consumed */
                #pragma unroll
                for (int j = 0; j < 6; j++) {
                    int i4 = tid + j * 256;
                    cp16(sm + OFF_W2S + i4 * 4, w2 + ky * 6144 + i4 * 4);
                }
                cp_commit();
            }
            cp_wait0();
            __syncthreads();                     /* ky=0: also orders act1 */

            if (ky == 2) {                       /* prefetch w3 tap0 into scratch */
                #pragma unroll
                for (int j = 0; j < 8; j++) {
                    int i4 = (tid + j * 256) * 4;
                    float* dst = (i4 < 6912) ? (sm + i4)
                                             : (sm + OFF_ACT3 + 8 + (i4 - 6912));
                    cp16(dst, w3 + i4);
                }
                cp_commit();
            }

            const float* ab = sm + OFF_ACT1 + (2 * oy + ky) * 84 + (mh * 4) * 10 + 2 * ox;
            #pragma unroll 4
            for (int ic = 0; ic < 32; ic++) {
                const float* ai = ab + ic * 756;
                float2 a01[4]; float a2[4];
                #pragma unroll
                for (int i = 0; i < 4; i++) {
                    a01[i] = *(const float2*)(ai + i * 10);
                    a2[i]  = ai[i * 10 + 2];
                }
                #pragma unroll
                for (int kx = 0; kx < 3; kx++) {
                    const float* wb = sm + OFF_W2S + kx * 2048 + ic * 64 + oc0;
                    ulonglong2 wA = *(const ulonglong2*)(wb);
                    ulonglong2 wB = *(const ulonglong2*)(wb + 4);
                    #pragma unroll
                    for (int i = 0; i < 4; i++) {
                        float av = (kx == 0) ? a01[i].x : (kx == 1) ? a01[i].y : a2[i];
                        u64 aa = pack2(av, av);
                        fma2(acc[i][0], aa, wA.x);
                        fma2(acc[i][1], aa, wA.y);
                        fma2(acc[i][2], aa, wB.x);
                        fma2(acc[i][3], aa, wB.y);
                    }
                }
            }
        }
        const int pos = (ox & 1) ? 4 + (ox >> 1) : (ox >> 1);   /* parity group */
        #pragma unroll
        for (int j = 0; j < 4; j++) {
            int oc = oc0 + 2 * j;
            float bi0 = s_b[32 + oc], bi1 = s_b[32 + oc + 1];
            #pragma unroll
            for (int i = 0; i < 4; i++) {
                int p = mh * 4 + i;
                float lo, hi; unpack2(acc[i][j], lo, hi);
                float* o = sm + OFF_ACT2 + oc * 192 + p * 24 + oy * 6 + pos;
                o[0]   = fmaxf(lo + bi0, 0.f);
                o[192] = fmaxf(hi + bi1, 0.f);
            }
        }
    }

    /* ---- conv3: warp = 32oc x (4p x 4px); full-row weight loads; pipelined:
           tap0 from scratch; tap t+1 issued before tap t computes; wd chunk0
           issued at tap8's top into tap7's freed buffer ---- */
    {
        const int ocgrp = wid & 3;
        const int pgrp  = wid >> 2;
        const int seg   = lane & 7;
        const int mg    = lane >> 3;
        const int p     = pgrp * 4 + mg;
        const int oc    = ocgrp * 32 + seg * 4;
        u64 acc[4][2];
        #pragma unroll
        for (int i = 0; i < 4; i++) { acc[i][0] = 0ull; acc[i][1] = 0ull; }

        cp_wait0();                 /* tap0 arrived */
        __syncthreads();            /* act2 stores + tap0 visible to all */

        /* issue tap1 -> ACT1+0 */
        #pragma unroll
        for (int j = 0; j < 8; j++) {
            int i4 = tid + j * 256;
            cp16(sm + OFF_ACT1 + i4 * 4, w3 + 8192 + i4 * 4);
        }
        cp_commit();

        /* ---- tap0 (ky=0, kx=0) from scratch ---- */
        {
            const float* ap = sm + OFF_ACT2 + p * 24;
            #pragma unroll 4
            for (int ic = 0; ic < 54; ic++) {
                ulonglong2 w = *(const ulonglong2*)(sm + ic * 128 + oc);
                float2 aA = *(const float2*)(ap + ic * 192);
                float2 aB = *(const float2*)(ap + ic * 192 + 12);
                u64 a00 = pack2(aA.x, aA.x), a01 = pack2(aA.y, aA.y);
                u64 a10 = pack2(aB.x, aB.x), a11 = pack2(aB.y, aB.y);
                fma2(acc[0][0], a00, w.x); fma2(acc[0][1], a00, w.y);
                fma2(acc[1][0], a01, w.x); fma2(acc[1][1], a01, w.y);
                fma2(acc[2][0], a10, w.x); fma2(acc[2][1], a10, w.y);
                fma2(acc[3][0], a11, w.x); fma2(acc[3][1], a11, w.y);
            }
            #pragma unroll
            for (int ic = 54; ic < 64; ic++) {
                ulonglong2 w = *(const ulonglong2*)(sm + OFF_ACT3 + 8 + (ic - 54) * 128 + oc);
                float2 aA = *(const float2*)(ap + ic * 192);
                float2 aB = *(const float2*)(ap + ic * 192 + 12);
                u64 a00 = pack2(aA.x, aA.x), a01 = pack2(aA.y, aA.y);
                u64 a10 = pack2(aB.x, aB.x), a11 = pack2(aB.y, aB.y);
                fma2(acc[0][0], a00, w.x); fma2(acc[0][1], a00, w.y);
                fma2(acc[1][0], a01, w.x); fma2(acc[1][1], a01, w.y);
                fma2(acc[2][0], a10, w.x); fma2(acc[2][1], a10, w.y);
                fma2(acc[3][0], a11, w.x); fma2(acc[3][1], a11, w.y);
            }
        }

        /* ---- taps 1..8: buffers at ACT1 + ((t-1)&1)*8224 ---- */
        #pragma unroll 1
        for (int t = 1; t < 9; t++) {
            cp_wait0();             /* tap t ready */
            __syncthreads();        /* visible; buffer (t&1) free for reuse */
            if (t <= 7) {           /* issue tap t+1 */
                #pragma unroll
                for (int j = 0; j < 8; j++) {
                    int i4 = tid + j * 256;
                    cp16(sm + OFF_ACT1 + (t & 1) * 8224 + i4 * 4,
                         w3 + (t + 1) * 8192 + i4 * 4);
                }
            } else {                /* issue wd chunk0 -> ACT1+0 */
                #pragma unroll
                for (int j = 0; j < 8; j++) {
                    int idx = tid + j * 256;
                    int row = idx >> 4;
                    int col = (idx & 15) * 4;
                    int kqs = row >> 6, rr = row & 63;
                    cp16(sm + OFF_ACT1 + kqs * 4104 + rr * 64 + col,
                         wd + (kqs * 128 + rr) * 64 + col);
                }
            }
            cp_commit();

            int ky = t / 3, kx = t - (t / 3) * 3;
            const float* wbb = sm + OFF_ACT1 + ((t - 1) & 1) * 8224;
            const float* ap = sm + OFF_ACT2 + p * 24 + ky * 6;
            if (kx < 2) {
                if (ky < 2) {
                    #pragma unroll 4
                    for (int ic = 0; ic < 64; ic++) {
                        ulonglong2 w = *(const ulonglong2*)(wbb + ic * 128 + oc);
                        float2 aA = *(const float2*)(ap + ic * 192 + kx * 4);
                        float2 aB = *(const float2*)(ap + ic * 192 + 12 + kx * 4);
                        u64 a00 = pack2(aA.x, aA.x), a01 = pack2(aA.y, aA.y);
                        u64 a10 = pack2(aB.x, aB.x), a11 = pack2(aB.y, aB.y);
                        fma2(acc[0][0], a00, w.x); fma2(acc[0][1], a00, w.y);
                        fma2(acc[1][0], a01, w.x); fma2(acc[1][1], a01, w.y);
                        fma2(acc[2][0], a10, w.x); fma2(acc[2][1], a10, w.y);
                        fma2(acc[3][0], a11, w.x); fma2(acc[3][1], a11, w.y);
                    }
                } else {
                    #pragma unroll 4
                    for (int ic = 0; ic < 64; ic++) {
                        ulonglong2 w = *(const ulonglong2*)(wbb + ic * 128 + oc);
                        float2 aA = *(const float2*)(ap + ic * 192 + kx * 4);
                        u64 a00 = pack2(aA.x, aA.x), a01 = pack2(aA.y, aA.y);
                        fma2(acc[0][0], a00, w.x); fma2(acc[0][1], a00, w.y);
                        fma2(acc[1][0], a01, w.x); fma2(acc[1][1], a01, w.y);
                    }
                }
            } else {
                if (ky < 2) {
                    #pragma unroll 4
                    for (int ic = 0; ic < 64; ic++) {
                        ulonglong2 w = *(const ulonglong2*)(wbb + ic * 128 + oc);
                        float s0 = ap[ic * 192 + 1];
                        float s1 = ap[ic * 192 + 13];
                        u64 a00 = pack2(s0, s0), a10 = pack2(s1, s1);
                        fma2(acc[0][0], a00, w.x); fma2(acc[0][1], a00, w.y);
                        fma2(acc[2][0], a10, w.x); fma2(acc[2][1], a10, w.y);
                    }
                } else {
                    #pragma unroll 4
                    for (int ic = 0; ic < 64; ic++) {
                        ulonglong2 w = *(const ulonglong2*)(wbb + ic * 128 + oc);
                        float s0 = ap[ic * 192 + 1];
                        u64 a00 = pack2(s0, s0);
                        fma2(acc[0][0], a00, w.x); fma2(acc[0][1], a00, w.y);
                    }
                }
            }
        }
        #pragma unroll
        for (int px = 0; px < 4; px++) {
            float v0, v1, v2, v3;
            unpack2(acc[px][0], v0, v1);
            unpack2(acc[px][1], v2, v3);
            float* o = sm + OFF_ACT3 + p * 516 + px * 129 + oc;
            o[0] = fmaxf(v0 + s_b[96 + oc],     0.f);
            o[1] = fmaxf(v1 + s_b[96 + oc + 1], 0.f);
            o[2] = fmaxf(v2 + s_b[96 + oc + 2], 0.f);
            o[3] = fmaxf(v3 + s_b[96 + oc + 3], 0.f);
        }
    }

    /* ---- dense 512->64: chunk0 prefetched (ACT1+0); chunk1 overlapped ---- */
    {
        const int oc0 = wid * 8;
        const int kq = lane >> 3, pl = lane & 7;
        u64 acc[4] = {0ull, 0ull, 0ull, 0ull};

        cp_wait0();                 /* wd chunk0 */
        __syncthreads();            /* + conv3 epilogue ACT3 stores visible */

        /* issue chunk1 -> ACT1+8224 */
        #pragma unroll
        for (int j = 0; j < 8; j++) {
            int idx = tid + j * 256;
            int row = idx >> 4;
            int col = (idx & 15) * 4;
            int kqs = row >> 6, rr = row & 63;
            cp16(sm + OFF_ACT1 + 8224 + kqs * 4104 + rr * 64 + col,
                 wd + (kqs * 128 + 64 + rr) * 64 + col);
        }
        cp_commit();

        /* chunk 0 */
        {
            const float* xp = sm + OFF_ACT3 + pl * 516 + kq * 129;
            const float* wp = sm + OFF_ACT1 + kq * 4104 + oc0;
            #pragma unroll 8
            for (int kk = 0; kk < 64; kk++) {
                float x = xp[kk];
                u64 xx = pack2(x, x);
                ulonglong2 w01 = *(const ulonglong2*)(wp + kk * 64);
                ulonglong2 w23 = *(const ulonglong2*)(wp + kk * 64 + 4);
                fma2(acc[0], xx, w01.x); fma2(acc[1], xx, w01.y);
                fma2(acc[2], xx, w23.x); fma2(acc[3], xx, w23.y);
            }
        }
        cp_wait0();
        __syncthreads();
        /* chunk 1 */
        {
            const float* xp = sm + OFF_ACT3 + pl * 516 + kq * 129 + 64;
            const float* wp = sm + OFF_ACT1 + 8224 + kq * 4104 + oc0;
            #pragma unroll 8
            for (int kk = 0; kk < 64; kk++) {
                float x = xp[kk];
                u64 xx = pack2(x, x);
                ulonglong2 w01 = *(const ulonglong2*)(wp + kk * 64);
                ulonglong2 w23 = *(const ulonglong2*)(wp + kk * 64 + 4);
                fma2(acc[0], xx, w01.x); fma2(acc[1], xx, w01.y);
                fma2(acc[2], xx, w23.x); fma2(acc[3], xx, w23.y);
            }
        }
        float r[8];
        #pragma unroll
        for (int j = 0; j < 4; j++) unpack2(acc[j], r[2 * j], r[2 * j + 1]);
        #pragma unroll
        for (int j = 0; j < 8; j++) {
            r[j] += __shfl_xor_sync(0xffffffffu, r[j], 8);
            r[j] += __shfl_xor_sync(0xffffffffu, r[j], 16);
        }
        if (kq == 0) {
            #pragma unroll
            for (int j = 0; j < 8; j++) {
                int e = oc0 + j;
                sm[OFF_V + pl * 64 + e] = r[j] + s_b[224 + e];
            }
        }
    }
    __syncthreads();

    /* ---- head: vn2, stage c_x (stride 65), d2 -> ow -> atomics ---- */
    if (tid < GP) {
        float a = 0.f;
        const float* vp = sm + OFF_V + tid * 64;
        #pragma unroll 8
        for (int e = 0; e < 64; e++) a = fmaf(vp[e], vp[e], a);
        sm[OFF_VN2 + tid] = a;
    }
    for (int i = tid; i < 8192; i += T) {
        int k = i >> 6, e = i & 63;
        sm[OFF_ACT1 + k * 65 + e] = c_x[i];
    }
    __syncthreads();

    {
        float inv_s2 = 1.f / (sigma[0] * sigma[0]);
        int k = tid & 127, pg = tid >> 7;
        u64 d01 = pack2(sm[OFF_VN2 + pg * 4],     sm[OFF_VN2 + pg * 4 + 1]);
        u64 d23 = pack2(sm[OFF_VN2 + pg * 4 + 2], sm[OFF_VN2 + pg * 4 + 3]);
        const u64 neg2 = pack2(-2.f, -2.f);
        const float* vp = sm + OFF_V + pg * 256;
        const float* ck = sm + OFF_ACT1 + k * 65;
        #pragma unroll 8
        for (int e = 0; e < 64; e++) {
            float cv = ck[e];
            u64 cc = pack2(cv, cv);
            u64 v01 = pack2(vp[e],       vp[64 + e]);
            u64 v23 = pack2(vp[128 + e], vp[192 + e]);
            u64 t01 = cc, t23 = cc;
            fma2(t01, neg2, v01);
            fma2(t23, neg2, v23);
            fma2(d01, cc, t01);
            fma2(d23, cc, t23);
        }
        float d[4];
        unpack2(d01, d[0], d[1]);
        unpack2(d23, d[2], d[3]);
        int b0 = (g0 + pg * 4)     / NPP;
        int b3 = (g0 + pg * 4 + 3) / NPP;
        float accA = 0.f, accB = 0.f;
        float cwk = s_cw[k];
        #pragma unroll
        for (int pp = 0; pp < 4; pp++) {
            float dd = fmaxf(d[pp], 0.f);
            float owv = fmaxf(cwk * __expf(-dd * inv_s2), 1e-10f);
            int b = (g0 + pg * 4 + pp) / NPP;
            if (b == b0) accA += owv; else accB += owv;
        }
        atomicAdd(&g_ysum[b0 * 128 + k], accA);
        if (b3 != b0) atomicAdd(&g_ysum[b3 * 128 + k], accB);
    }

    /* ---- last-CTA finalize ---- */
    __syncthreads();
    __shared__ unsigned s_rank;
    if (tid == 0) {
        __threadfence();
        s_rank = atomicAdd(&g_count, 1u);
    }
    __syncthreads();
    if (s_rank == NBLK - 1) {
        __threadfence();
        float* s_y   = sm + OFF_RS;
        float* yv2   = s_y + 2048;
        float* rsum  = yv2 + 1280;
        for (int i = tid; i < NB * 128; i += T) {
            s_y[i] = g_ysum[i];
            g_ysum[i] = 0.f;
        }
        if (tid == 0) g_count = 0u;
        __syncthreads();
        for (int k = tid; k < 128; k += T) {
            float n2 = 0.f;
            #pragma unroll
            for (int i = 0; i < 10; i++) { float c = c_y[k * 10 + i]; n2 = fmaf(c, c, n2); }
            float inv = 1.f / n2;
            #pragma unroll
            for (int i = 0; i < 10; i++) { float c = c_y[k * 10 + i]; yv2[k * 10 + i] = c * c * inv; }
        }
        if (tid < NB) {
            float s = 0.f;
            for (int k = 0; k < 128; k++) s += s_y[tid * 128 + k];
            rsum[tid] = s;
        }
        __syncthreads();
        if (tid < NB * 10) {
            int b = tid / 10, i = tid % 10;
            float a = 0.f;
            for (int k = 0; k < 128; k++) a = fmaf(s_y[b * 128 + k], yv2[k * 10 + i], a);
            out[tid] = a / rsum[b];
        }
    }
}

extern "C" void kernel_launch(void* const* d_in, const int* in_sizes, int n_in,
                              void* d_out, int out_size) {
    (void)in_sizes; (void)n_in; (void)out_size;
    const float* images = (const float*)d_in[0];
    const float* w1     = (const float*)d_in[1];
    const float* b1     = (const float*)d_in[2];
    const float* w2     = (const float*)d_in[3];
    const float* b2     = (const float*)d_in[4];
    const float* w3     = (const float*)d_in[5];
    const float* b3     = (const float*)d_in[6];
    const float* wd     = (const float*)d_in[7];
    const float* bd     = (const float*)d_in[8];
    const float* c_x    = (const float*)d_in[9];
    const float* c_y    = (const float*)d_in[10];
    const float* comp_w = (const float*)d_in[11];
    const float* sigma  = (const float*)d_in[12];
    float* out = (float*)d_out;

    cudaFuncSetAttribute(main_kernel, cudaFuncAttributeMaxDynamicSharedMemorySize, SMEM_BYTES);

    main_kernel<<<NBLK, T, SMEM_BYTES>>>(images, w1, b1, w2, b2, w3, b3,
                                         wd, bd, c_x, c_y, comp_w, sigma, out);
}

// round 15
// speedup vs baseline: 1.1092x; 1.0225x over previous
#include <cuda_runtime.h>
#include <math.h>

typedef unsigned long long u64;

#define T 256
#define GP 8
#define NB   16
#define NPQ  45
#define NPP  (NPQ*NPQ)
#define NTOT (NB*NPP)
#define NBLK (NTOT/GP)      /* 4050 CTAs */

/* float offsets in dynamic smem */
#define OFF_RS    0         /* 6936  : resized planar; later w3-tap0 scratch (54 rows) */
#define OFF_ACT1  6936      /* 24192 : [32oc][9iy][p*10+ix]; reused w3/wd               */
#define OFF_ACT2  31128     /* 12288 : parity rows [64oc][8p][4iy][6]; RAW+h overlay    */
#define OFF_RAW   31128     /* 1536  : [3][8p][64] (dead before conv2 epilogue)         */
#define OFF_H     33176     /* 3072  : resize h-buffer [3][8p][8iy][16ox] (transient)   */
#define OFF_ACT3  43416     /* 4128  : [8p][516]; +8..1287 = w3-tap0 scratch rows 54-63 */
#define OFF_W2S   47544     /* 6144  : w2 ky-group buffer (3 taps)                      */
#define OFF_W1    53688     /* 864                                                      */
#define OFF_V     54552     /* 512   : [p][64]                                          */
#define OFF_B     55064     /* 288   : b1 b2 b3 bd                                      */
#define OFF_CW    55352     /* 128                                                      */
#define OFF_VN2   55480     /* 8                                                        */
#define SMEM_FLOATS 55488
#define SMEM_BYTES  (SMEM_FLOATS * 4)   /* 221952 */

__device__ float    g_ysum[NB * 128];
__device__ unsigned g_count;

/* ---- packed fp32x2 ---- */
__device__ __forceinline__ u64 pack2(float lo, float hi) {
    u64 r; asm("mov.b64 %0, {%1, %2};" : "=l"(r) : "f"(lo), "f"(hi)); return r;
}
__device__ __forceinline__ void unpack2(u64 v, float& lo, float& hi) {
    asm("mov.b64 {%0, %1}, %2;" : "=f"(lo), "=f"(hi) : "l"(v));
}
__device__ __forceinline__ void fma2(u64& d, u64 a, u64 b) {
    asm("fma.rn.f32x2 %0, %1, %2, %0;" : "+l"(d) : "l"(a), "l"(b));
}

__device__ __forceinline__ void cp16(float* dst, const float* src) {
    unsigned s = (unsigned)__cvta_generic_to_shared(dst);
    asm volatile("cp.async.cg.shared.global [%0], [%1], 16;\n" :: "r"(s), "l"(src));
}
__device__ __forceinline__ void cp_commit() { asm volatile("cp.async.commit_group;\n"); }
__device__ __forceinline__ void cp_wait0()  { asm volatile("cp.async.wait_group 0;\n"); }

/* jax.image.resize 'linear' 8->16 */
__device__ __forceinline__ void rtab(int i, int& a0, int& a1, float& w0, float& w1) {
    if (i == 0)       { a0 = 0; a1 = 0; w0 = 1.f;   w1 = 0.f;   }
    else if (i == 15) { a0 = 7; a1 = 7; w0 = 1.f;   w1 = 0.f;   }
    else if (i & 1)   { int m = i >> 1; a0 = m;     a1 = m + 1; w0 = 0.75f; w1 = 0.25f; }
    else              { int m = i >> 1; a0 = m - 1; a1 = m;     w0 = 0.25f; w1 = 0.75f; }
}

__global__ __launch_bounds__(T, 1)
void main_kernel(const float* __restrict__ images,
                 const float* __restrict__ w1, const float* __restrict__ b1,
                 const float* __restrict__ w2, const float* __restrict__ b2,
                 const float* __restrict__ w3, const float* __restrict__ b3,
                 const float* __restrict__ wd, const float* __restrict__ bd,
                 const float* __restrict__ c_x, const float* __restrict__ c_y,
                 const float* __restrict__ comp_w, const float* __restrict__ sigma,
                 float* __restrict__ out)
{
    extern __shared__ float sm[];
    const int tid  = threadIdx.x;
    const int g0   = blockIdx.x * GP;
    const int wid  = tid >> 5;
    const int lane = tid & 31;

    float* s_b  = sm + OFF_B;
    float* s_cw = sm + OFF_CW;

    /* ---- init ---- */
    for (int i = tid; i < 864; i += T) sm[OFF_W1 + i] = w1[i];
    if (tid < 32)  s_b[tid]       = b1[tid];
    if (tid < 64)  s_b[32 + tid]  = b2[tid];
    if (tid < 128) s_b[96 + tid]  = b3[tid];
    if (tid < 64)  s_b[224 + tid] = bd[tid];
    if (tid < 128) s_cw[tid]      = comp_w[tid];
    for (int i = tid; i < OFF_ACT2 / 4; i += T)          /* zero rs + act1 */
        ((float4*)sm)[i] = make_float4(0.f, 0.f, 0.f, 0.f);

    for (int i = tid; i < 1536; i += T) {
        int c = i >> 9, rem = i & 511, p = rem >> 6, r = rem & 63;
        int iy = r >> 3, ix = r & 7;
        int g = g0 + p, b = g / NPP, pp = g % NPP;
        int py = pp / NPQ, px = pp % NPQ;
        sm[OFF_RAW + i] = images[((b * 96 + py * 2 + iy) * 96 + px * 2 + ix) * 3 + c];
    }
    __syncthreads();

    /* ---- resize pass 1 (horizontal): h[c][p][iy][ox] ---- */
    for (int i = tid; i < 3072; i += T) {
        int c = i >> 10, rem = i & 1023, p = rem >> 7, r2 = rem & 127;
        int iy = r2 >> 4, ox = r2 & 15;
        int ax0, ax1; float wx0, wx1;
        rtab(ox, ax0, ax1, wx0, wx1);
        const float* rp = sm + OFF_RAW + c * 512 + p * 64 + iy * 8;
        sm[OFF_H + i] = wx0 * rp[ax0] + wx1 * rp[ax1];
    }
    __syncthreads();

    /* ---- resize pass 2 (vertical) into padded 17x17 planes ---- */
    for (int i = tid; i < 6144; i += T) {
        int c = i >> 11, rem = i & 2047, p = rem >> 8, r = rem & 255;
        int oy = r >> 4, ox = r & 15;
        int ay0, ay1; float wy0, wy1;
        rtab(oy, ay0, ay1, wy0, wy1);
        const float* hp = sm + OFF_H + c * 1024 + p * 128;
        sm[OFF_RS + c * 2312 + p * 289 + oy * 17 + ox] =
            wy0 * hp[ay0 * 16 + ox] + wy1 * hp[ay1 * 16 + ox];
    }
    __syncthreads();

    /* ---- prefetch w2 ky-group 0 during conv1 ---- */
    #pragma unroll
    for (int j = 0; j < 6; j++) {
        int i4 = tid + j * 256;
        cp16(sm + OFF_W2S + i4 * 4, w2 + i4 * 4);
    }
    cp_commit();

    /* ---- conv1: M=512 N=32 K=27, TM=8, TN=8; writes act1 [oc][iy][p*10+ix] ---- */
    {
        const int mt = tid >> 2, ng = tid & 3;
        const int p = mt >> 3, oy = mt & 7;
        u64 acc[8][4];
        #pragma unroll
        for (int i = 0; i < 8; i++)
            #pragma unroll
            for (int j = 0; j < 4; j++) acc[i][j] = 0ull;

        #pragma unroll 1
        for (int ky = 0; ky < 3; ky++)
        #pragma unroll 1
        for (int kx = 0; kx < 3; kx++) {
            #pragma unroll
            for (int c = 0; c < 3; c++) {
                const float* ap = sm + OFF_RS + c * 2312 + p * 289 + (2 * oy + ky) * 17 + kx;
                u64 aa[8];
                #pragma unroll
                for (int ox = 0; ox < 8; ox++) { float av = ap[2 * ox]; aa[ox] = pack2(av, av); }
                const ulonglong2* wp2 = (const ulonglong2*)(sm + OFF_W1 + ((ky * 3 + kx) * 3 + c) * 32 + ng * 8);
                ulonglong2 q0 = wp2[0], q1 = wp2[1];
                u64 bb[4] = {q0.x, q0.y, q1.x, q1.y};
                #pragma unroll
                for (int ox = 0; ox < 8; ox++)
                    #pragma unroll
                    for (int j = 0; j < 4; j++)
                        fma2(acc[ox][j], aa[ox], bb[j]);
            }
        }
        #pragma unroll
        for (int j = 0; j < 4; j++) {
            int oc0 = ng * 8 + 2 * j;
            float bi0 = s_b[oc0], bi1 = s_b[oc0 + 1];
            float* op0 = sm + OFF_ACT1 + oc0 * 756 + oy * 84 + p * 10;
            float* op1 = op0 + 756;
            #pragma unroll
            for (int ox = 0; ox < 8; ox++) {
                float lo, hi; unpack2(acc[ox][j], lo, hi);
                op0[ox] = fmaxf(lo + bi0, 0.f);
                op1[ox] = fmaxf(hi + bi1, 0.f);
            }
        }
    }

    /* ---- conv2: warp=(mh, ocq); lane=(ocg, pix); acts float2+scalar.
           At ky==2, prefetch w3 tap0 into scratch (RS rows 0-53, ACT3+8 rows 54-63) ---- */
    {
        const int mh  = wid >> 2;
        const int ocq = wid & 3;
        const int ocg = lane & 1;
        const int pix = lane >> 1;
        const int oy = pix >> 2, ox = pix & 3;
        const int oc0 = ocq * 16 + ocg * 8;
        u64 acc[4][4];
        #pragma unroll
        for (int i = 0; i < 4; i++)
            #pragma unroll
            for (int j = 0; j < 4; j++) acc[i][j] = 0ull;

        #pragma unroll 1
        for (int ky = 0; ky < 3; ky++) {
            if (ky > 0) {
                __syncthreads();                 /* prior group fully consumed */
                #pragma unroll
                for (int j = 0; j < 6; j++) {
                    int i4 = tid + j * 256;
                    cp16(sm + OFF_W2S + i4 * 4, w2 + ky * 6144 + i4 * 4);
                }
                cp_commit();
            }
            cp_wait0();
            __syncthreads();                     /* ky=0: also orders act1 */

            if (ky == 2) {                       /* prefetch w3 tap0 into scratch */
                #pragma unroll
                for (int j = 0; j < 8; j++) {
                    int i4 = (tid + j * 256) * 4;
                    float* dst = (i4 < 6912) ? (sm + i4)
                                             : (sm + OFF_ACT3 + 8 + (i4 - 6912));
                    cp16(dst, w3 + i4);
                }
                cp_commit();
            }

            const float* ab = sm + OFF_ACT1 + (2 * oy + ky) * 84 + (mh * 4) * 10 + 2 * ox;
            #pragma unroll 4
            for (int ic = 0; ic < 32; ic++) {
                const float* ai = ab + ic * 756;
                float2 a01[4]; float a2[4];
                #pragma unroll
                for (int i = 0; i < 4; i++) {
                    a01[i] = *(const float2*)(ai + i * 10);
                    a2[i]  = ai[i * 10 + 2];
                }
                #pragma unroll
                for (int kx = 0; kx < 3; kx++) {
                    const float* wb = sm + OFF_W2S + kx * 2048 + ic * 64 + oc0;
                    ulonglong2 wA = *(const ulonglong2*)(wb);
                    ulonglong2 wB = *(const ulonglong2*)(wb + 4);
                    #pragma unroll
                    for (int i = 0; i < 4; i++) {
                        float av = (kx == 0) ? a01[i].x : (kx == 1) ? a01[i].y : a2[i];
                        u64 aa = pack2(av, av);
                        fma2(acc[i][0], aa, wA.x);
                        fma2(acc[i][1], aa, wA.y);
                        fma2(acc[i][2], aa, wB.x);
                        fma2(acc[i][3], aa, wB.y);
                    }
                }
            }
        }
        const int pos = (ox & 1) ? 4 + (ox >> 1) : (ox >> 1);   /* parity group */
        #pragma unroll
        for (int j = 0; j < 4; j++) {
            int oc = oc0 + 2 * j;
            float bi0 = s_b[32 + oc], bi1 = s_b[32 + oc + 1];
            #pragma unroll
            for (int i = 0; i < 4; i++) {
                int p = mh * 4 + i;
                float lo, hi; unpack2(acc[i][j], lo, hi);
                float* o = sm + OFF_ACT2 + oc * 192 + p * 24 + oy * 6 + pos;
                o[0]   = fmaxf(lo + bi0, 0.f);
                o[192] = fmaxf(hi + bi1, 0.f);
            }
        }
    }

    /* ---- conv3: warp = 32oc x (4p x 4px); full-row weight loads; pipelined ---- */
    {
        const int ocgrp = wid & 3;
        const int pgrp  = wid >> 2;
        const int seg   = lane & 7;
        const int mg    = lane >> 3;
        const int p     = pgrp * 4 + mg;
        const int oc    = ocgrp * 32 + seg * 4;
        u64 acc[4][2];
        #pragma unroll
        for (int i = 0; i < 4; i++) { acc[i][0] = 0ull; acc[i][1] = 0ull; }

        cp_wait0();                 /* tap0 arrived */
        __syncthreads();            /* act2 stores + tap0 visible to all */

        /* issue tap1 -> ACT1+0 */
        #pragma unroll
        for (int j = 0; j < 8; j++) {
            int i4 = tid + j * 256;
            cp16(sm + OFF_ACT1 + i4 * 4, w3 + 8192 + i4 * 4);
        }
        cp_commit();

        /* ---- tap0 (ky=0, kx=0) from scratch ---- */
        {
            const float* ap = sm + OFF_ACT2 + p * 24;
            #pragma unroll 4
            for (int ic = 0; ic < 54; ic++) {
                ulonglong2 w = *(const ulonglong2*)(sm + ic * 128 + oc);
                float2 aA = *(const float2*)(ap + ic * 192);
                float2 aB = *(const float2*)(ap + ic * 192 + 12);
                u64 a00 = pack2(aA.x, aA.x), a01 = pack2(aA.y, aA.y);
                u64 a10 = pack2(aB.x, aB.x), a11 = pack2(aB.y, aB.y);
                fma2(acc[0][0], a00, w.x); fma2(acc[0][1], a00, w.y);
                fma2(acc[1][0], a01, w.x); fma2(acc[1][1], a01, w.y);
                fma2(acc[2][0], a10, w.x); fma2(acc[2][1], a10, w.y);
                fma2(acc[3][0], a11, w.x); fma2(acc[3][1], a11, w.y);
            }
            #pragma unroll
            for (int ic = 54; ic < 64; ic++) {
                ulonglong2 w = *(const ulonglong2*)(sm + OFF_ACT3 + 8 + (ic - 54) * 128 + oc);
                float2 aA = *(const float2*)(ap + ic * 192);
                float2 aB = *(const float2*)(ap + ic * 192 + 12);
                u64 a00 = pack2(aA.x, aA.x), a01 = pack2(aA.y, aA.y);
                u64 a10 = pack2(aB.x, aB.x), a11 = pack2(aB.y, aB.y);
                fma2(acc[0][0], a00, w.x); fma2(acc[0][1], a00, w.y);
                fma2(acc[1][0], a01, w.x); fma2(acc[1][1], a01, w.y);
                fma2(acc[2][0], a10, w.x); fma2(acc[2][1], a10, w.y);
                fma2(acc[3][0], a11, w.x); fma2(acc[3][1], a11, w.y);
            }
        }

        /* ---- taps 1..8: buffers at ACT1 + ((t-1)&1)*8224 ---- */
        #pragma unroll 1
        for (int t = 1; t < 9; t++) {
            cp_wait0();             /* tap t ready */
            __syncthreads();        /* visible; buffer (t&1) free for reuse */
            if (t <= 7) {           /* issue tap t+1 */
                #pragma unroll
                for (int j = 0; j < 8; j++) {
                    int i4 = tid + j * 256;
                    cp16(sm + OFF_ACT1 + (t & 1) * 8224 + i4 * 4,
                         w3 + (t + 1) * 8192 + i4 * 4);
                }
            } else {                /* issue wd chunk0 -> ACT1+0 */
                #pragma unroll
                for (int j = 0; j < 8; j++) {
                    int idx = tid + j * 256;
                    int row = idx >> 4;
                    int col = (idx & 15) * 4;
                    int kqs = row >> 6, rr = row & 63;
                    cp16(sm + OFF_ACT1 + kqs * 4104 + rr * 64 + col,
                         wd + (kqs * 128 + rr) * 64 + col);
                }
            }
            cp_commit();

            int ky = t / 3, kx = t - (t / 3) * 3;
            const float* wbb = sm + OFF_ACT1 + ((t - 1) & 1) * 8224;
            const float* ap = sm + OFF_ACT2 + p * 24 + ky * 6;
            if (kx < 2) {
                if (ky < 2) {
                    #pragma unroll 4
                    for (int ic = 0; ic < 64; ic++) {
                        ulonglong2 w = *(const ulonglong2*)(wbb + ic * 128 + oc);
                        float2 aA = *(const float2*)(ap + ic * 192 + kx * 4);
                        float2 aB = *(const float2*)(ap + ic * 192 + 12 + kx * 4);
                        u64 a00 = pack2(aA.x, aA.x), a01 = pack2(aA.y, aA.y);
                        u64 a10 = pack2(aB.x, aB.x), a11 = pack2(aB.y, aB.y);
                        fma2(acc[0][0], a00, w.x); fma2(acc[0][1], a00, w.y);
                        fma2(acc[1][0], a01, w.x); fma2(acc[1][1], a01, w.y);
                        fma2(acc[2][0], a10, w.x); fma2(acc[2][1], a10, w.y);
                        fma2(acc[3][0], a11, w.x); fma2(acc[3][1], a11, w.y);
                    }
                } else {
                    #pragma unroll 4
                    for (int ic = 0; ic < 64; ic++) {
                        ulonglong2 w = *(const ulonglong2*)(wbb + ic * 128 + oc);
                        float2 aA = *(const float2*)(ap + ic * 192 + kx * 4);
                        u64 a00 = pack2(aA.x, aA.x), a01 = pack2(aA.y, aA.y);
                        fma2(acc[0][0], a00, w.x); fma2(acc[0][1], a00, w.y);
                        fma2(acc[1][0], a01, w.x); fma2(acc[1][1], a01, w.y);
                    }
                }
            } else {
                if (ky < 2) {
                    #pragma unroll 4
                    for (int ic = 0; ic < 64; ic++) {
                        ulonglong2 w = *(const ulonglong2*)(wbb + ic * 128 + oc);
                        float s0 = ap[ic * 192 + 1];
                        float s1 = ap[ic * 192 + 13];
                        u64 a00 = pack2(s0, s0), a10 = pack2(s1, s1);
                        fma2(acc[0][0], a00, w.x); fma2(acc[0][1], a00, w.y);
                        fma2(acc[2][0], a10, w.x); fma2(acc[2][1], a10, w.y);
                    }
                } else {
                    #pragma unroll 4
                    for (int ic = 0; ic < 64; ic++) {
                        ulonglong2 w = *(const ulonglong2*)(wbb + ic * 128 + oc);
                        float s0 = ap[ic * 192 + 1];
                        u64 a00 = pack2(s0, s0);
                        fma2(acc[0][0], a00, w.x); fma2(acc[0][1], a00, w.y);
                    }
                }
            }
        }
        #pragma unroll
        for (int px = 0; px < 4; px++) {
            float v0, v1, v2, v3;
            unpack2(acc[px][0], v0, v1);
            unpack2(acc[px][1], v2, v3);
            float* o = sm + OFF_ACT3 + p * 516 + px * 129 + oc;
            o[0] = fmaxf(v0 + s_b[96 + oc],     0.f);
            o[1] = fmaxf(v1 + s_b[96 + oc + 1], 0.f);
            o[2] = fmaxf(v2 + s_b[96 + oc + 2], 0.f);
            o[3] = fmaxf(v3 + s_b[96 + oc + 3], 0.f);
        }
    }

    /* ---- dense 512->64: chunk0 prefetched (ACT1+0); chunk1 overlapped ---- */
    {
        const int oc0 = wid * 8;
        const int kq = lane >> 3, pl = lane & 7;
        u64 acc[4] = {0ull, 0ull, 0ull, 0ull};

        cp_wait0();                 /* wd chunk0 */
        __syncthreads();            /* + conv3 epilogue ACT3 stores visible */

        /* issue chunk1 -> ACT1+8224 */
        #pragma unroll
        for (int j = 0; j < 8; j++) {
            int idx = tid + j * 256;
            int row = idx >> 4;
            int col = (idx & 15) * 4;
            int kqs = row >> 6, rr = row & 63;
            cp16(sm + OFF_ACT1 + 8224 + kqs * 4104 + rr * 64 + col,
                 wd + (kqs * 128 + 64 + rr) * 64 + col);
        }
        cp_commit();

        /* chunk 0 */
        {
            const float* xp = sm + OFF_ACT3 + pl * 516 + kq * 129;
            const float* wp = sm + OFF_ACT1 + kq * 4104 + oc0;
            #pragma unroll 8
            for (int kk = 0; kk < 64; kk++) {
                float x = xp[kk];
                u64 xx = pack2(x, x);
                ulonglong2 w01 = *(const ulonglong2*)(wp + kk * 64);
                ulonglong2 w23 = *(const ulonglong2*)(wp + kk * 64 + 4);
                fma2(acc[0], xx, w01.x); fma2(acc[1], xx, w01.y);
                fma2(acc[2], xx, w23.x); fma2(acc[3], xx, w23.y);
            }
        }
        cp_wait0();
        __syncthreads();
        /* chunk 1 */
        {
            const float* xp = sm + OFF_ACT3 + pl * 516 + kq * 129 + 64;
            const float* wp = sm + OFF_ACT1 + 8224 + kq * 4104 + oc0;
            #pragma unroll 8
            for (int kk = 0; kk < 64; kk++) {
                float x = xp[kk];
                u64 xx = pack2(x, x);
                ulonglong2 w01 = *(const ulonglong2*)(wp + kk * 64);
                ulonglong2 w23 = *(const ulonglong2*)(wp + kk * 64 + 4);
                fma2(acc[0], xx, w01.x); fma2(acc[1], xx, w01.y);
                fma2(acc[2], xx, w23.x); fma2(acc[3], xx, w23.y);
            }
        }
        float r[8];
        #pragma unroll
        for (int j = 0; j < 4; j++) unpack2(acc[j], r[2 * j], r[2 * j + 1]);
        #pragma unroll
        for (int j = 0; j < 8; j++) {
            r[j] += __shfl_xor_sync(0xffffffffu, r[j], 8);
            r[j] += __shfl_xor_sync(0xffffffffu, r[j], 16);
        }
        if (kq == 0) {
            #pragma unroll
            for (int j = 0; j < 8; j++) {
                int e = oc0 + j;
                sm[OFF_V + pl * 64 + e] = r[j] + s_b[224 + e];
            }
        }
    }
    __syncthreads();

    /* ---- head: vn2, then d2 with c_x read directly via __ldg float4 ---- */
    if (tid < GP) {
        float a = 0.f;
        const float* vp = sm + OFF_V + tid * 64;
        #pragma unroll 8
        for (int e = 0; e < 64; e++) a = fmaf(vp[e], vp[e], a);
        sm[OFF_VN2 + tid] = a;
    }
    __syncthreads();

    {
        float inv_s2 = 1.f / (sigma[0] * sigma[0]);
        int k = tid & 127, pg = tid >> 7;
        u64 d01 = pack2(sm[OFF_VN2 + pg * 4],     sm[OFF_VN2 + pg * 4 + 1]);
        u64 d23 = pack2(sm[OFF_VN2 + pg * 4 + 2], sm[OFF_VN2 + pg * 4 + 3]);
        const u64 neg2 = pack2(-2.f, -2.f);
        const float* vp = sm + OFF_V + pg * 256;
        const float4* cxp = (const float4*)(c_x + k * 64);
        #pragma unroll 4
        for (int e4 = 0; e4 < 16; e4++) {
            float4 cv4 = __ldg(cxp + e4);
            float cva[4] = {cv4.x, cv4.y, cv4.z, cv4.w};
            #pragma unroll
            for (int j = 0; j < 4; j++) {
                int e = e4 * 4 + j;
                float cv = cva[j];
                u64 cc = pack2(cv, cv);
                u64 v01 = pack2(vp[e],       vp[64 + e]);
                u64 v23 = pack2(vp[128 + e], vp[192 + e]);
                u64 t01 = cc, t23 = cc;
                fma2(t01, neg2, v01);
                fma2(t23, neg2, v23);
                fma2(d01, cc, t01);
                fma2(d23, cc, t23);
            }
        }
        float d[4];
        unpack2(d01, d[0], d[1]);
        unpack2(d23, d[2], d[3]);
        int b0 = (g0 + pg * 4)     / NPP;
        int b3 = (g0 + pg * 4 + 3) / NPP;
        float accA = 0.f, accB = 0.f;
        float cwk = s_cw[k];
        #pragma unroll
        for (int pp = 0; pp < 4; pp++) {
            float dd = fmaxf(d[pp], 0.f);
            float owv = fmaxf(cwk * __expf(-dd * inv_s2), 1e-10f);
            int b = (g0 + pg * 4 + pp) / NPP;
            if (b == b0) accA += owv; else accB += owv;
        }
        atomicAdd(&g_ysum[b0 * 128 + k], accA);
        if (b3 != b0) atomicAdd(&g_ysum[b3 * 128 + k], accB);
    }

    /* ---- last-CTA finalize ---- */
    __syncthreads();
    __shared__ unsigned s_rank;
    if (tid == 0) {
        __threadfence();
        s_rank = atomicAdd(&g_count, 1u);
    }
    __syncthreads();
    if (s_rank == NBLK - 1) {
        __threadfence();
        float* s_y   = sm + OFF_RS;
        float* yv2   = s_y + 2048;
        float* rsum  = yv2 + 1280;
        for (int i = tid; i < NB * 128; i += T) {
            s_y[i] = g_ysum[i];
            g_ysum[i] = 0.f;
        }
        if (tid == 0) g_count = 0u;
        __syncthreads();
        for (int k = tid; k < 128; k += T) {
            float n2 = 0.f;
            #pragma unroll
            for (int i = 0; i < 10; i++) { float c = c_y[k * 10 + i]; n2 = fmaf(c, c, n2); }
            float inv = 1.f / n2;
            #pragma unroll
            for (int i = 0; i < 10; i++) { float c = c_y[k * 10 + i]; yv2[k * 10 + i] = c * c * inv; }
        }
        if (tid < NB) {
            float s = 0.f;
            for (int k = 0; k < 128; k++) s += s_y[tid * 128 + k];
            rsum[tid] = s;
        }
        __syncthreads();
        if (tid < NB * 10) {
            int b = tid / 10, i = tid % 10;
            float a = 0.f;
            for (int k = 0; k < 128; k++) a = fmaf(s_y[b * 128 + k], yv2[k * 10 + i], a);
            out[tid] = a / rsum[b];
        }
    }
}

extern "C" void kernel_launch(void* const* d_in, const int* in_sizes, int n_in,
                              void* d_out, int out_size) {
    (void)in_sizes; (void)n_in; (void)out_size;
    const float* images = (const float*)d_in[0];
    const float* w1     = (const float*)d_in[1];
    const float* b1     = (const float*)d_in[2];
    const float* w2     = (const float*)d_in[3];
    const float* b2     = (const float*)d_in[4];
    const float* w3     = (const float*)d_in[5];
    const float* b3     = (const float*)d_in[6];
    const float* wd     = (const float*)d_in[7];
    const float* bd     = (const float*)d_in[8];
    const float* c_x    = (const float*)d_in[9];
    const float* c_y    = (const float*)d_in[10];
    const float* comp_w = (const float*)d_in[11];
    const float* sigma  = (const float*)d_in[12];
    float* out = (float*)d_out;

    cudaFuncSetAttribute(main_kernel, cudaFuncAttributeMaxDynamicSharedMemorySize, SMEM_BYTES);

    main_kernel<<<NBLK, T, SMEM_BYTES>>>(images, w1, b1, w2, b2, w3, b3,
                                         wd, bd, c_x, c_y, comp_w, sigma, out);
}

// round 16
// speedup vs baseline: 1.1227x; 1.0122x over previous
#include <cuda_runtime.h>
#include <math.h>

typedef unsigned long long u64;

#define T 256
#define GP 8
#define NB   16
#define NPQ  45
#define NPP  (NPQ*NPQ)
#define NTOT (NB*NPP)
#define NBLK (NTOT/GP)      /* 4050 CTAs */

#define A1S  758            /* act1 oc-plane stride (even, 8*A1S%32=16) */

/* float offsets in dynamic smem */
#define OFF_RS    0         /* 6936  : resized planar; later w3-tap0 scratch (54 rows) */
#define OFF_ACT1  6936      /* 24254 : [32oc][9iy][p*10+ix] stride A1S; reused w3/wd   */
#define OFF_ACT2  31192     /* 12288 : parity rows [64oc][8p][4iy][6]; RAW+h overlay   */
#define OFF_RAW   31192     /* 1536  : [3][8p][64] (dead before conv2 epilogue)        */
#define OFF_H     33240     /* 3072  : resize h-buffer [3][8p][8iy][16ox] (transient)  */
#define OFF_ACT3  43480     /* 4128  : [8p][516]; +8..1287 = w3-tap0 scratch rows 54-63*/
#define OFF_W2S   47608     /* 6144  : w2 ky-group buffer (3 taps)                     */
#define OFF_W1    53752     /* 864                                                      */
#define OFF_V     54616     /* 512   : [p][64]                                          */
#define OFF_B     55128     /* 288   : b1 b2 b3 bd                                      */
#define OFF_CW    55416     /* 128                                                      */
#define OFF_VN2   55544     /* 8                                                        */
#define SMEM_FLOATS 55552
#define SMEM_BYTES  (SMEM_FLOATS * 4)   /* 222208 <= 232448 */

__device__ float    g_ysum[NB * 128];
__device__ unsigned g_count;

/* ---- packed fp32x2 ---- */
__device__ __forceinline__ u64 pack2(float lo, float hi) {
    u64 r; asm("mov.b64 %0, {%1, %2};" : "=l"(r) : "f"(lo), "f"(hi)); return r;
}
__device__ __forceinline__ void unpack2(u64 v, float& lo, float& hi) {
    asm("mov.b64 {%0, %1}, %2;" : "=f"(lo), "=f"(hi) : "l"(v));
}
__device__ __forceinline__ void fma2(u64& d, u64 a, u64 b) {
    asm("fma.rn.f32x2 %0, %1, %2, %0;" : "+l"(d) : "l"(a), "l"(b));
}

__device__ __forceinline__ void cp16(float* dst, const float* src) {
    unsigned s = (unsigned)__cvta_generic_to_shared(dst);
    asm volatile("cp.async.cg.shared.global [%0], [%1], 16;\n" :: "r"(s), "l"(src));
}
__device__ __forceinline__ void cp_commit() { asm volatile("cp.async.commit_group;\n"); }
__device__ __forceinline__ void cp_wait0()  { asm volatile("cp.async.wait_group 0;\n"); }

/* jax.image.resize 'linear' 8->16 */
__device__ __forceinline__ void rtab(int i, int& a0, int& a1, float& w0, float& w1) {
    if (i == 0)       { a0 = 0; a1 = 0; w0 = 1.f;   w1 = 0.f;   }
    else if (i == 15) { a0 = 7; a1 = 7; w0 = 1.f;   w1 = 0.f;   }
    else if (i & 1)   { int m = i >> 1; a0 = m;     a1 = m + 1; w0 = 0.75f; w1 = 0.25f; }
    else              { int m = i >> 1; a0 = m - 1; a1 = m;     w0 = 0.25f; w1 = 0.75f; }
}

__global__ __launch_bounds__(T, 1)
void main_kernel(const float* __restrict__ images,
                 const float* __restrict__ w1, const float* __restrict__ b1,
                 const float* __restrict__ w2, const float* __restrict__ b2,
                 const float* __restrict__ w3, const float* __restrict__ b3,
                 const float* __restrict__ wd, const float* __restrict__ bd,
                 const float* __restrict__ c_x, const float* __restrict__ c_y,
                 const float* __restrict__ comp_w, const float* __restrict__ sigma,
                 float* __restrict__ out)
{
    extern __shared__ float sm[];
    const int tid  = threadIdx.x;
    const int g0   = blockIdx.x * GP;
    const int wid  = tid >> 5;
    const int lane = tid & 31;

    float* s_b  = sm + OFF_B;
    float* s_cw = sm + OFF_CW;

    /* ---- init ---- */
    for (int i = tid; i < 864; i += T) sm[OFF_W1 + i] = w1[i];
    if (tid < 32)  s_b[tid]       = b1[tid];
    if (tid < 64)  s_b[32 + tid]  = b2[tid];
    if (tid < 128) s_b[96 + tid]  = b3[tid];
    if (tid < 64)  s_b[224 + tid] = bd[tid];
    if (tid < 128) s_cw[tid]      = comp_w[tid];
    for (int i = tid; i < OFF_ACT2 / 2; i += T) {        /* zero rs + act1 (scalar: odd size) */
        sm[2 * i]     = 0.f;
        sm[2 * i + 1] = 0.f;
    }

    for (int i = tid; i < 1536; i += T) {
        int c = i >> 9, rem = i & 511, p = rem >> 6, r = rem & 63;
        int iy = r >> 3, ix = r & 7;
        int g = g0 + p, b = g / NPP, pp = g % NPP;
        int py = pp / NPQ, px = pp % NPQ;
        sm[OFF_RAW + i] = images[((b * 96 + py * 2 + iy) * 96 + px * 2 + ix) * 3 + c];
    }
    __syncthreads();

    /* ---- resize pass 1 (horizontal): h[c][p][iy][ox] ---- */
    for (int i = tid; i < 3072; i += T) {
        int c = i >> 10, rem = i & 1023, p = rem >> 7, r2 = rem & 127;
        int iy = r2 >> 4, ox = r2 & 15;
        int ax0, ax1; float wx0, wx1;
        rtab(ox, ax0, ax1, wx0, wx1);
        const float* rp = sm + OFF_RAW + c * 512 + p * 64 + iy * 8;
        sm[OFF_H + i] = wx0 * rp[ax0] + wx1 * rp[ax1];
    }
    __syncthreads();

    /* ---- resize pass 2 (vertical) into padded 17x17 planes ---- */
    for (int i = tid; i < 6144; i += T) {
        int c = i >> 11, rem = i & 2047, p = rem >> 8, r = rem & 255;
        int oy = r >> 4, ox = r & 15;
        int ay0, ay1; float wy0, wy1;
        rtab(oy, ay0, ay1, wy0, wy1);
        const float* hp = sm + OFF_H + c * 1024 + p * 128;
        sm[OFF_RS + c * 2312 + p * 289 + oy * 17 + ox] =
            wy0 * hp[ay0 * 16 + ox] + wy1 * hp[ay1 * 16 + ox];
    }
    __syncthreads();

    /* ---- prefetch w2 ky-group 0 during conv1 ---- */
    #pragma unroll
    for (int j = 0; j < 6; j++) {
        int i4 = tid + j * 256;
        cp16(sm + OFF_W2S + i4 * 4, w2 + i4 * 4);
    }
    cp_commit();

    /* ---- conv1: M=512 N=32 K=27, TM=8, TN=8; writes act1 [oc][iy][p*10+ix] ---- */
    {
        const int mt = tid >> 2, ng = tid & 3;
        const int p = mt >> 3, oy = mt & 7;
        u64 acc[8][4];
        #pragma unroll
        for (int i = 0; i < 8; i++)
            #pragma unroll
            for (int j = 0; j < 4; j++) acc[i][j] = 0ull;

        #pragma unroll 1
        for (int ky = 0; ky < 3; ky++)
        #pragma unroll 1
        for (int kx = 0; kx < 3; kx++) {
            #pragma unroll
            for (int c = 0; c < 3; c++) {
                const float* ap = sm + OFF_RS + c * 2312 + p * 289 + (2 * oy + ky) * 17 + kx;
                u64 aa[8];
                #pragma unroll
                for (int ox = 0; ox < 8; ox++) { float av = ap[2 * ox]; aa[ox] = pack2(av, av); }
                const ulonglong2* wp2 = (const ulonglong2*)(sm + OFF_W1 + ((ky * 3 + kx) * 3 + c) * 32 + ng * 8);
                ulonglong2 q0 = wp2[0], q1 = wp2[1];
                u64 bb[4] = {q0.x, q0.y, q1.x, q1.y};
                #pragma unroll
                for (int ox = 0; ox < 8; ox++)
                    #pragma unroll
                    for (int j = 0; j < 4; j++)
                        fma2(acc[ox][j], aa[ox], bb[j]);
            }
        }
        #pragma unroll
        for (int j = 0; j < 4; j++) {
            int oc0 = ng * 8 + 2 * j;
            float bi0 = s_b[oc0], bi1 = s_b[oc0 + 1];
            float* op0 = sm + OFF_ACT1 + oc0 * A1S + oy * 84 + p * 10;
            float* op1 = op0 + A1S;
            #pragma unroll
            for (int ox = 0; ox < 8; ox++) {
                float lo, hi; unpack2(acc[ox][j], lo, hi);
                op0[ox] = fmaxf(lo + bi0, 0.f);
                op1[ox] = fmaxf(hi + bi1, 0.f);
            }
        }
    }

    /* ---- conv2: warp=(mh, ocq); lane=(ocg, pix); acts float2+scalar.
           At ky==2, prefetch w3 tap0 into scratch (RS rows 0-53, ACT3+8 rows 54-63) ---- */
    {
        const int mh  = wid >> 2;
        const int ocq = wid & 3;
        const int ocg = lane & 1;
        const int pix = lane >> 1;
        const int oy = pix >> 2, ox = pix & 3;
        const int oc0 = ocq * 16 + ocg * 8;
        u64 acc[4][4];
        #pragma unroll
        for (int i = 0; i < 4; i++)
            #pragma unroll
            for (int j = 0; j < 4; j++) acc[i][j] = 0ull;

        #pragma unroll 1
        for (int ky = 0; ky < 3; ky++) {
            if (ky > 0) {
                __syncthreads();                 /* prior group fully consumed */
                #pragma unroll
                for (int j = 0; j < 6; j++) {
                    int i4 = tid + j * 256;
                    cp16(sm + OFF_W2S + i4 * 4, w2 + ky * 6144 + i4 * 4);
                }
                cp_commit();
            }
            cp_wait0();
            __syncthreads();                     /* ky=0: also orders act1 */

            if (ky == 2) {                       /* prefetch w3 tap0 into scratch */
                #pragma unroll
                for (int j = 0; j < 8; j++) {
                    int i4 = (tid + j * 256) * 4;
                    float* dst = (i4 < 6912) ? (sm + i4)
                                             : (sm + OFF_ACT3 + 8 + (i4 - 6912));
                    cp16(dst, w3 + i4);
                }
                cp_commit();
            }

            const float* ab = sm + OFF_ACT1 + (2 * oy + ky) * 84 + (mh * 4) * 10 + 2 * ox;
            #pragma unroll 4
            for (int ic = 0; ic < 32; ic++) {
                const float* ai = ab + ic * A1S;
                float2 a01[4]; float a2[4];
                #pragma unroll
                for (int i = 0; i < 4; i++) {
                    a01[i] = *(const float2*)(ai + i * 10);
                    a2[i]  = ai[i * 10 + 2];
                }
                #pragma unroll
                for (int kx = 0; kx < 3; kx++) {
                    const float* wb = sm + OFF_W2S + kx * 2048 + ic * 64 + oc0;
                    ulonglong2 wA = *(const ulonglong2*)(wb);
                    ulonglong2 wB = *(const ulonglong2*)(wb + 4);
                    #pragma unroll
                    for (int i = 0; i < 4; i++) {
                        float av = (kx == 0) ? a01[i].x : (kx == 1) ? a01[i].y : a2[i];
                        u64 aa = pack2(av, av);
                        fma2(acc[i][0], aa, wA.x);
                        fma2(acc[i][1], aa, wA.y);
                        fma2(acc[i][2], aa, wB.x);
                        fma2(acc[i][3], aa, wB.y);
                    }
                }
            }
        }
        const int pos = (ox & 1) ? 4 + (ox >> 1) : (ox >> 1);   /* parity group */
        #pragma unroll
        for (int j = 0; j < 4; j++) {
            int oc = oc0 + 2 * j;
            float bi0 = s_b[32 + oc], bi1 = s_b[32 + oc + 1];
            #pragma unroll
            for (int i = 0; i < 4; i++) {
                int p = mh * 4 + i;
                float lo, hi; unpack2(acc[i][j], lo, hi);
                float* o = sm + OFF_ACT2 + oc * 192 + p * 24 + oy * 6 + pos;
                o[0]   = fmaxf(lo + bi0, 0.f);
                o[192] = fmaxf(hi + bi1, 0.f);
            }
        }
    }

    /* ---- conv3: warp = 32oc x (4p x 4px); full-row weight loads; pipelined ---- */
    {
        const int ocgrp = wid & 3;
        const int pgrp  = wid >> 2;
        const int seg   = lane & 7;
        const int mg    = lane >> 3;
        const int p     = pgrp * 4 + mg;
        const int oc    = ocgrp * 32 + seg * 4;
        u64 acc[4][2];
        #pragma unroll
        for (int i = 0; i < 4; i++) { acc[i][0] = 0ull; acc[i][1] = 0ull; }

        cp_wait0();                 /* tap0 arrived */
        __syncthreads();            /* act2 stores + tap0 visible to all */

        /* issue tap1 -> ACT1+0 */
        #pragma unroll
        for (int j = 0; j < 8; j++) {
            int i4 = tid + j * 256;
            cp16(sm + OFF_ACT1 + i4 * 4, w3 + 8192 + i4 * 4);
        }
        cp_commit();

        /* ---- tap0 (ky=0, kx=0) from scratch ---- */
        {
            const float* ap = sm + OFF_ACT2 + p * 24;
            #pragma unroll 8
            for (int ic = 0; ic < 54; ic++) {
                ulonglong2 w = *(const ulonglong2*)(sm + ic * 128 + oc);
                float2 aA = *(const float2*)(ap + ic * 192);
                float2 aB = *(const float2*)(ap + ic * 192 + 12);
                u64 a00 = pack2(aA.x, aA.x), a01 = pack2(aA.y, aA.y);
                u64 a10 = pack2(aB.x, aB.x), a11 = pack2(aB.y, aB.y);
                fma2(acc[0][0], a00, w.x); fma2(acc[0][1], a00, w.y);
                fma2(acc[1][0], a01, w.x); fma2(acc[1][1], a01, w.y);
                fma2(acc[2][0], a10, w.x); fma2(acc[2][1], a10, w.y);
                fma2(acc[3][0], a11, w.x); fma2(acc[3][1], a11, w.y);
            }
            #pragma unroll
            for (int ic = 54; ic < 64; ic++) {
                ulonglong2 w = *(const ulonglong2*)(sm + OFF_ACT3 + 8 + (ic - 54) * 128 + oc);
                float2 aA = *(const float2*)(ap + ic * 192);
                float2 aB = *(const float2*)(ap + ic * 192 + 12);
                u64 a00 = pack2(aA.x, aA.x), a01 = pack2(aA.y, aA.y);
                u64 a10 = pack2(aB.x, aB.x), a11 = pack2(aB.y, aB.y);
                fma2(acc[0][0], a00, w.x); fma2(acc[0][1], a00, w.y);
                fma2(acc[1][0], a01, w.x); fma2(acc[1][1], a01, w.y);
                fma2(acc[2][0], a10, w.x); fma2(acc[2][1], a10, w.y);
                fma2(acc[3][0], a11, w.x); fma2(acc[3][1], a11, w.y);
            }
        }

        /* ---- taps 1..8: buffers at ACT1 + ((t-1)&1)*8224 ---- */
        #pragma unroll 1
        for (int t = 1; t < 9; t++) {
            cp_wait0();             /* tap t ready */
            __syncthreads();        /* visible; buffer (t&1) free for reuse */
            if (t <= 7) {           /* issue tap t+1 */
                #pragma unroll
                for (int j = 0; j < 8; j++) {
                    int i4 = tid + j * 256;
                    cp16(sm + OFF_ACT1 + (t & 1) * 8224 + i4 * 4,
                         w3 + (t + 1) * 8192 + i4 * 4);
                }
            } else {                /* issue wd chunk0 -> ACT1+0 */
                #pragma unroll
                for (int j = 0; j < 8; j++) {
                    int idx = tid + j * 256;
                    int row = idx >> 4;
                    int col = (idx & 15) * 4;
                    int kqs = row >> 6, rr = row & 63;
                    cp16(sm + OFF_ACT1 + kqs * 4104 + rr * 64 + col,
                         wd + (kqs * 128 + rr) * 64 + col);
                }
            }
            cp_commit();

            int ky = t / 3, kx = t - (t / 3) * 3;
            const float* wbb = sm + OFF_ACT1 + ((t - 1) & 1) * 8224;
            const float* ap = sm + OFF_ACT2 + p * 24 + ky * 6;
            if (kx < 2) {
                if (ky < 2) {
                    #pragma unroll 8
                    for (int ic = 0; ic < 64; ic++) {
                        ulonglong2 w = *(const ulonglong2*)(wbb + ic * 128 + oc);
                        float2 aA = *(const float2*)(ap + ic * 192 + kx * 4);
                        float2 aB = *(const float2*)(ap + ic * 192 + 12 + kx * 4);
                        u64 a00 = pack2(aA.x, aA.x), a01 = pack2(aA.y, aA.y);
                        u64 a10 = pack2(aB.x, aB.x), a11 = pack2(aB.y, aB.y);
                        fma2(acc[0][0], a00, w.x); fma2(acc[0][1], a00, w.y);
                        fma2(acc[1][0], a01, w.x); fma2(acc[1][1], a01, w.y);
                        fma2(acc[2][0], a10, w.x); fma2(acc[2][1], a10, w.y);
                        fma2(acc[3][0], a11, w.x); fma2(acc[3][1], a11, w.y);
                    }
                } else {
                    #pragma unroll 8
                    for (int ic = 0; ic < 64; ic++) {
                        ulonglong2 w = *(const ulonglong2*)(wbb + ic * 128 + oc);
                        float2 aA = *(const float2*)(ap + ic * 192 + kx * 4);
                        u64 a00 = pack2(aA.x, aA.x), a01 = pack2(aA.y, aA.y);
                        fma2(acc[0][0], a00, w.x); fma2(acc[0][1], a00, w.y);
                        fma2(acc[1][0], a01, w.x); fma2(acc[1][1], a01, w.y);
                    }
                }
            } else {
                if (ky < 2) {
                    #pragma unroll 8
                    for (int ic = 0; ic < 64; ic++) {
                        ulonglong2 w = *(const ulonglong2*)(wbb + ic * 128 + oc);
                        float s0 = ap[ic * 192 + 1];
                        float s1 = ap[ic * 192 + 13];
                        u64 a00 = pack2(s0, s0), a10 = pack2(s1, s1);
                        fma2(acc[0][0], a00, w.x); fma2(acc[0][1], a00, w.y);
                        fma2(acc[2][0], a10, w.x); fma2(acc[2][1], a10, w.y);
                    }
                } else {
                    #pragma unroll 8
                    for (int ic = 0; ic < 64; ic++) {
                        ulonglong2 w = *(const ulonglong2*)(wbb + ic * 128 + oc);
                        float s0 = ap[ic * 192 + 1];
                        u64 a00 = pack2(s0, s0);
                        fma2(acc[0][0], a00, w.x); fma2(acc[0][1], a00, w.y);
                    }
                }
            }
        }
        #pragma unroll
        for (int px = 0; px < 4; px++) {
            float v0, v1, v2, v3;
            unpack2(acc[px][0], v0, v1);
            unpack2(acc[px][1], v2, v3);
            float* o = sm + OFF_ACT3 + p * 516 + px * 129 + oc;
            o[0] = fmaxf(v0 + s_b[96 + oc],     0.f);
            o[1] = fmaxf(v1 + s_b[96 + oc + 1], 0.f);
            o[2] = fmaxf(v2 + s_b[96 + oc + 2], 0.f);
            o[3] = fmaxf(v3 + s_b[96 + oc + 3], 0.f);
        }
    }

    /* ---- dense 512->64: chunk0 prefetched (ACT1+0); chunk1 overlapped ---- */
    {
        const int oc0 = wid * 8;
        const int kq = lane >> 3, pl = lane & 7;
        u64 acc[4] = {0ull, 0ull, 0ull, 0ull};

        cp_wait0();                 /* wd chunk0 */
        __syncthreads();            /* + conv3 epilogue ACT3 stores visible */

        /* issue chunk1 -> ACT1+8224 */
        #pragma unroll
        for (int j = 0; j < 8; j++) {
            int idx = tid + j * 256;
            int row = idx >> 4;
            int col = (idx & 15) * 4;
            int kqs = row >> 6, rr = row & 63;
            cp16(sm + OFF_ACT1 + 8224 + kqs * 4104 + rr * 64 + col,
                 wd + (kqs * 128 + 64 + rr) * 64 + col);
        }
        cp_commit();

        /* chunk 0 */
        {
            const float* xp = sm + OFF_ACT3 + pl * 516 + kq * 129;
            const float* wp = sm + OFF_ACT1 + kq * 4104 + oc0;
            #pragma unroll 8
            for (int kk = 0; kk < 64; kk++) {
                float x = xp[kk];
                u64 xx = pack2(x, x);
                ulonglong2 w01 = *(const ulonglong2*)(wp + kk * 64);
                ulonglong2 w23 = *(const ulonglong2*)(wp + kk * 64 + 4);
                fma2(acc[0], xx, w01.x); fma2(acc[1], xx, w01.y);
                fma2(acc[2], xx, w23.x); fma2(acc[3], xx, w23.y);
            }
        }
        cp_wait0();
        __syncthreads();
        /* chunk 1 */
        {
            const float* xp = sm + OFF_ACT3 + pl * 516 + kq * 129 + 64;
            const float* wp = sm + OFF_ACT1 + 8224 + kq * 4104 + oc0;
            #pragma unroll 8
            for (int kk = 0; kk < 64; kk++) {
                float x = xp[kk];
                u64 xx = pack2(x, x);
                ulonglong2 w01 = *(const ulonglong2*)(wp + kk * 64);
                ulonglong2 w23 = *(const ulonglong2*)(wp + kk * 64 + 4);
                fma2(acc[0], xx, w01.x); fma2(acc[1], xx, w01.y);
                fma2(acc[2], xx, w23.x); fma2(acc[3], xx, w23.y);
            }
        }
        float r[8];
        #pragma unroll
        for (int j = 0; j < 4; j++) unpack2(acc[j], r[2 * j], r[2 * j + 1]);
        #pragma unroll
        for (int j = 0; j < 8; j++) {
            r[j] += __shfl_xor_sync(0xffffffffu, r[j], 8);
            r[j] += __shfl_xor_sync(0xffffffffu, r[j], 16);
        }
        if (kq == 0) {
            #pragma unroll
            for (int j = 0; j < 8; j++) {
                int e = oc0 + j;
                sm[OFF_V + pl * 64 + e] = r[j] + s_b[224 + e];
            }
        }
    }
    __syncthreads();

    /* ---- head: vn2, then d2 with c_x read directly via __ldg float4 ---- */
    if (tid < GP) {
        float a = 0.f;
        const float* vp = sm + OFF_V + tid * 64;
        #pragma unroll 8
        for (int e = 0; e < 64; e++) a = fmaf(vp[e], vp[e], a);
        sm[OFF_VN2 + tid] = a;
    }
    __syncthreads();

    {
        float inv_s2 = 1.f / (sigma[0] * sigma[0]);
        int k = tid & 127, pg = tid >> 7;
        u64 d01 = pack2(sm[OFF_VN2 + pg * 4],     sm[OFF_VN2 + pg * 4 + 1]);
        u64 d23 = pack2(sm[OFF_VN2 + pg * 4 + 2], sm[OFF_VN2 + pg * 4 + 3]);
        const u64 neg2 = pack2(-2.f, -2.f);
        const float* vp = sm + OFF_V + pg * 256;
        const float4* cxp = (const float4*)(c_x + k * 64);
        #pragma unroll 4
        for (int e4 = 0; e4 < 16; e4++) {
            float4 cv4 = __ldg(cxp + e4);
            float cva[4] = {cv4.x, cv4.y, cv4.z, cv4.w};
            #pragma unroll
            for (int j = 0; j < 4; j++) {
                int e = e4 * 4 + j;
                float cv = cva[j];
                u64 cc = pack2(cv, cv);
                u64 v01 = pack2(vp[e],       vp[64 + e]);
                u64 v23 = pack2(vp[128 + e], vp[192 + e]);
                u64 t01 = cc, t23 = cc;
                fma2(t01, neg2, v01);
                fma2(t23, neg2, v23);
                fma2(d01, cc, t01);
                fma2(d23, cc, t23);
            }
        }
        float d[4];
        unpack2(d01, d[0], d[1]);
        unpack2(d23, d[2], d[3]);
        int b0 = (g0 + pg * 4)     / NPP;
        int b3 = (g0 + pg * 4 + 3) / NPP;
        float accA = 0.f, accB = 0.f;
        float cwk = s_cw[k];
        #pragma unroll
        for (int pp = 0; pp < 4; pp++) {
            float dd = fmaxf(d[pp], 0.f);
            float owv = fmaxf(cwk * __expf(-dd * inv_s2), 1e-10f);
            int b = (g0 + pg * 4 + pp) / NPP;
            if (b == b0) accA += owv; else accB += owv;
        }
        atomicAdd(&g_ysum[b0 * 128 + k], accA);
        if (b3 != b0) atomicAdd(&g_ysum[b3 * 128 + k], accB);
    }

    /* ---- last-CTA finalize ---- */
    __syncthreads();
    __shared__ unsigned s_rank;
    if (tid == 0) {
        __threadfence();
        s_rank = atomicAdd(&g_count, 1u);
    }
    __syncthreads();
    if (s_rank == NBLK - 1) {
        __threadfence();
        float* s_y   = sm + OFF_RS;
        float* yv2   = s_y + 2048;
        float* rsum  = yv2 + 1280;
        for (int i = tid; i < NB * 128; i += T) {
            s_y[i] = g_ysum[i];
            g_ysum[i] = 0.f;
        }
        if (tid == 0) g_count = 0u;
        __syncthreads();
        for (int k = tid; k < 128; k += T) {
            float n2 = 0.f;
            #pragma unroll
            for (int i = 0; i < 10; i++) { float c = c_y[k * 10 + i]; n2 = fmaf(c, c, n2); }
            float inv = 1.f / n2;
            #pragma unroll
            for (int i = 0; i < 10; i++) { float c = c_y[k * 10 + i]; yv2[k * 10 + i] = c * c * inv; }
        }
        if (tid < NB) {
            float s = 0.f;
            for (int k = 0; k < 128; k++) s += s_y[tid * 128 + k];
            rsum[tid] = s;
        }
        __syncthreads();
        if (tid < NB * 10) {
            int b = tid / 10, i = tid % 10;
            float a = 0.f;
            for (int k = 0; k < 128; k++) a = fmaf(s_y[b * 128 + k], yv2[k * 10 + i], a);
            out[tid] = a / rsum[b];
        }
    }
}

extern "C" void kernel_launch(void* const* d_in, const int* in_sizes, int n_in,
                              void* d_out, int out_size) {
    (void)in_sizes; (void)n_in; (void)out_size;
    const float* images = (const float*)d_in[0];
    const float* w1     = (const float*)d_in[1];
    const float* b1     = (const float*)d_in[2];
    const float* w2     = (const float*)d_in[3];
    const float* b2     = (const float*)d_in[4];
    const float* w3     = (const float*)d_in[5];
    const float* b3     = (const float*)d_in[6];
    const float* wd     = (const float*)d_in[7];
    const float* bd     = (const float*)d_in[8];
    const float* c_x    = (const float*)d_in[9];
    const float* c_y    = (const float*)d_in[10];
    const float* comp_w = (const float*)d_in[11];
    const float* sigma  = (const float*)d_in[12];
    float* out = (float*)d_out;

    cudaFuncSetAttribute(main_kernel, cudaFuncAttributeMaxDynamicSharedMemorySize, SMEM_BYTES);

    main_kernel<<<NBLK, T, SMEM_BYTES>>>(images, w1, b1, w2, b2, w3, b3,
                                         wd, bd, c_x, c_y, comp_w, sigma, out);
}